// round 7
// baseline (speedup 1.0000x reference)
#include <cuda_runtime.h>

#define Bb 1024
#define Nn 16
#define Ii 256
#define Hh 1024
#define H3 3072

typedef unsigned long long u64;

// ---------------- scratch (device globals; no allocation allowed) ----------
__device__ __align__(256) float g_gie [Bb*Nn*H3];   // encoder input-gates (precomputed)
__device__ __align__(256) float g_henc[Bb*Nn*Hh];   // encoder hidden states
__device__ __align__(256) float g_w1xe[Bb*Nn*Hh];   // henc @ W1
__device__ __align__(256) float g_h   [Bb*Hh];      // current hidden
__device__ __align__(256) float g_heff[Bb*Hh];      // mixed hidden (decoder)
__device__ __align__(256) float g_gh  [Bb*H3];      // hidden-gates scratch
__device__ __align__(256) float g_gid [Bb*H3];      // decoder input-gates scratch
__device__ __align__(256) float g_hw2 [Bb*Hh];      // hidden @ W2
__device__ __align__(256) float g_inp [Bb*Ii];      // decoder input step
__device__ __align__(256) float g_u   [Bb*Nn];      // attention logits
__device__ __align__(256) float g_tgate[Nn*Bb];     // t_gate, layout [step][b]
__device__ __align__(256) int   g_idx  [Nn*Bb];     // idx_seq, layout [step][b]

// ---------------- helpers ---------------------------------------------------
__device__ __forceinline__ u64 dup2(float x) {
    u64 r; asm("mov.b64 %0, {%1, %1};" : "=l"(r) : "f"(x)); return r;
}
__device__ __forceinline__ void fma2(u64 &d, u64 a, u64 b) {
    asm("fma.rn.f32x2 %0, %1, %2, %0;" : "+l"(d) : "l"(a), "l"(b));
}
__device__ __forceinline__ float2 unpk(u64 v) {
    float2 f; asm("mov.b64 {%0, %1}, %2;" : "=f"(f.x), "=f"(f.y) : "l"(v)); return f;
}
__device__ __forceinline__ float fsig(float x) {
    return __fdividef(1.0f, 1.0f + __expf(-x));      // robust at +-inf
}
__device__ __forceinline__ float ftanh(float x) {
    // 1 - 2/(e^{2x}+1): exact limits at +-inf, ~1e-7 abs error
    return 1.0f - __fdividef(2.0f, __expf(2.0f * x) + 1.0f);
}

// ---------------- SGEMM -----------------------------------------------------
// C(M,N) = A(M,K) @ op(B) + bias,   BT: B is (N,K) row-major -> C = A@B^T
//                                  !BT: B is (K,N) row-major -> C = A@B
// GATE: A rows scaled by gate[m] before multiply.
// 128x128x16 tile, 256 threads, 8x8 per thread, packed f32x2 FMA.
template<bool BT, bool GATE>
__global__ __launch_bounds__(256, 2)
void sgemm(const float* __restrict__ A, const float* __restrict__ B,
           const float* __restrict__ bias, const float* __restrict__ gate,
           float* __restrict__ C, int M, int N, int K)
{
    __shared__ __align__(16) u64   As2[16][128];   // A values duplicated (lo=hi)
    __shared__ __align__(16) float Bs [16][128];

    const int tid = threadIdx.x;
    const int tx  = tid & 15;    // column group: cols tx*8 .. tx*8+7
    const int ty  = tid >> 4;    // row group:    rows ty*8 .. ty*8+7
    const int bm  = blockIdx.y * 128;
    const int bn  = blockIdx.x * 128;
    const int nkb = K >> 4;

    // load-index precompute
    const int ar0 = tid >> 2;          // A rows: ar0, ar0+64
    const int ac4 = tid & 3;           // A k-group (float4)
    const int bkr = tid >> 5;          // !BT: B k-rows: bkr, bkr+8
    const int bc4 = tid & 31;          // !BT: B col-group

    float4 pa[2], pb[2];
    float  ga[2] = {1.0f, 1.0f};
    if (GATE) { ga[0] = gate[bm + ar0]; ga[1] = gate[bm + ar0 + 64]; }

    auto loadA = [&](int kb) {
        pa[0] = *reinterpret_cast<const float4*>(A + (size_t)(bm + ar0     ) * K + kb*16 + ac4*4);
        pa[1] = *reinterpret_cast<const float4*>(A + (size_t)(bm + ar0 + 64) * K + kb*16 + ac4*4);
    };
    auto loadB = [&](int kb) {
        if (BT) {
            pb[0] = *reinterpret_cast<const float4*>(B + (size_t)(bn + ar0     ) * K + kb*16 + ac4*4);
            pb[1] = *reinterpret_cast<const float4*>(B + (size_t)(bn + ar0 + 64) * K + kb*16 + ac4*4);
        } else {
            pb[0] = *reinterpret_cast<const float4*>(B + (size_t)(kb*16 + bkr    ) * N + bn + bc4*4);
            pb[1] = *reinterpret_cast<const float4*>(B + (size_t)(kb*16 + bkr + 8) * N + bn + bc4*4);
        }
    };
    auto stash = [&]() {
        #pragma unroll
        for (int i = 0; i < 2; i++) {
            int row = ar0 + 64*i;
            float g = GATE ? ga[i] : 1.0f;
            float4 v = pa[i];
            As2[ac4*4+0][row] = dup2(v.x * g);
            As2[ac4*4+1][row] = dup2(v.y * g);
            As2[ac4*4+2][row] = dup2(v.z * g);
            As2[ac4*4+3][row] = dup2(v.w * g);
        }
        if (BT) {
            #pragma unroll
            for (int i = 0; i < 2; i++) {
                int row = ar0 + 64*i;
                float4 v = pb[i];
                Bs[ac4*4+0][row] = v.x;
                Bs[ac4*4+1][row] = v.y;
                Bs[ac4*4+2][row] = v.z;
                Bs[ac4*4+3][row] = v.w;
            }
        } else {
            *reinterpret_cast<float4*>(&Bs[bkr    ][bc4*4]) = pb[0];
            *reinterpret_cast<float4*>(&Bs[bkr + 8][bc4*4]) = pb[1];
        }
    };

    u64 acc[8][4];
    #pragma unroll
    for (int i = 0; i < 8; i++)
        #pragma unroll
        for (int p = 0; p < 4; p++) acc[i][p] = 0ull;

    loadA(0); loadB(0);
    stash();
    __syncthreads();

    for (int kb = 0; kb < nkb; kb++) {
        bool last = (kb == nkb - 1);
        if (!last) { loadA(kb + 1); loadB(kb + 1); }
        #pragma unroll
        for (int kk = 0; kk < 16; kk++) {
            const ulonglong2* arow = reinterpret_cast<const ulonglong2*>(&As2[kk][ty*8]);
            ulonglong2 a0 = arow[0], a1 = arow[1], a2 = arow[2], a3 = arow[3];
            const ulonglong2* brow = reinterpret_cast<const ulonglong2*>(&Bs[kk][tx*8]);
            ulonglong2 b0 = brow[0], b1 = brow[1];
            u64 av[8] = {a0.x, a0.y, a1.x, a1.y, a2.x, a2.y, a3.x, a3.y};
            u64 bv[4] = {b0.x, b0.y, b1.x, b1.y};
            #pragma unroll
            for (int i = 0; i < 8; i++)
                #pragma unroll
                for (int p = 0; p < 4; p++)
                    fma2(acc[i][p], av[i], bv[p]);
        }
        __syncthreads();
        if (!last) { stash(); __syncthreads(); }
    }

    #pragma unroll
    for (int i = 0; i < 8; i++) {
        float* crow = C + (size_t)(bm + ty*8 + i) * N + bn + tx*8;
        #pragma unroll
        for (int p = 0; p < 4; p++) {
            float2 vv = unpk(acc[i][p]);
            if (bias) {
                vv.x += bias[bn + tx*8 + 2*p];
                vv.y += bias[bn + tx*8 + 2*p + 1];
            }
            reinterpret_cast<float2*>(crow)[p] = vv;
        }
    }
}

// ---------------- small kernels ---------------------------------------------
__global__ void setup_kernel(const float* __restrict__ phis) {
    int id = blockIdx.x * 256 + threadIdx.x;       // B*N threads
    if (id >= Bb * Nn) return;
    int b = id >> 4, n = id & 15;
    const float* prow = phis + (size_t)(b * Nn + n) * Nn;
    float s = 0.0f;
    #pragma unroll
    for (int k = 0; k < Nn; k++) s += prow[k];
    int ns = (int)(s + 0.5f);                       // phis entries are exact 0/1
    g_tgate[n * Bb + b] = (n == 0) ? 1.0f : prow[n - 1];   // phis[b, n, n-1]
    g_idx[n * Bb + b] = (ns + n - 1) & (Nn - 1);
}

__global__ void zero_h_kernel() {
    g_h[blockIdx.x * 256 + threadIdx.x] = 0.0f;
}

__global__ void enc_combine(int t) {
    int id = blockIdx.x * 256 + threadIdx.x;       // B*H
    int b = id >> 10, h = id & 1023;
    float tg = g_tgate[t * Bb + b];
    float hg = tg * g_h[id];                        // gated previous hidden
    const float* gi = g_gie + (size_t)(b * Nn + t) * H3;
    const float* gh = g_gh  + (size_t)b * H3;       // already from gated h (GATE gemm)
    float r = fsig(gi[h] + gh[h]);
    float z = fsig(gi[Hh + h] + gh[Hh + h]);
    float g = ftanh(gi[2*Hh + h] + r * gh[2*Hh + h]);
    float hn = (1.0f - z) * g + z * hg;
    g_h[id] = hn;
    g_henc[(size_t)(b * Nn + t) * Hh + h] = hn;
}

__global__ void dec_init(const float* __restrict__ init_token) {
    int id = blockIdx.x * 256 + threadIdx.x;       // B*H
    int b = id >> 10, h = id & 1023;
    int idx = g_idx[b];                             // step-0 index = (Ns[b,0]-1)%N
    g_h[id] = g_henc[(size_t)(b * Nn + idx) * Hh + h];
    if (h < Ii) g_inp[b * Ii + h] = init_token[h];
}

__global__ void mix_kernel(const float* __restrict__ init_token, int t) {
    int id = blockIdx.x * 256 + threadIdx.x;       // B*H
    int b = id >> 10, h = id & 1023;
    float tg = g_tgate[t * Bb + b];
    int idx = g_idx[t * Bb + b];
    float ih = g_henc[(size_t)(b * Nn + idx) * Hh + h];
    g_heff[id] = tg * g_h[id] + (1.0f - tg) * ih;
    if (h < Ii) {
        int j = b * Ii + h;
        g_inp[j] = tg * g_inp[j] + (1.0f - tg) * init_token[h];
    }
}

__global__ void dec_combine() {
    int id = blockIdx.x * 256 + threadIdx.x;       // B*H
    int b = id >> 10, h = id & 1023;
    float hg = g_heff[id];
    const float* gi = g_gid + (size_t)b * H3;
    const float* gh = g_gh  + (size_t)b * H3;
    float r = fsig(gi[h] + gh[h]);
    float z = fsig(gi[Hh + h] + gh[Hh + h]);
    float g = ftanh(gi[2*Hh + h] + r * gh[2*Hh + h]);
    g_h[id] = (1.0f - z) * g + z * hg;
}

__global__ void u_kernel(const float* __restrict__ v) {
    int bn = blockIdx.x;                            // b*16 + n
    int b = bn >> 4;
    int i = threadIdx.x;                            // 256 threads x 4 h each
    float4 w  = reinterpret_cast<const float4*>(g_w1xe + (size_t)bn * Hh)[i];
    float4 hw = reinterpret_cast<const float4*>(g_hw2  + (size_t)b  * Hh)[i];
    float4 vv = reinterpret_cast<const float4*>(v)[i];
    float s = ftanh(w.x + hw.x) * vv.x + ftanh(w.y + hw.y) * vv.y
            + ftanh(w.z + hw.z) * vv.z + ftanh(w.w + hw.w) * vv.w;
    #pragma unroll
    for (int o = 16; o; o >>= 1) s += __shfl_xor_sync(0xffffffffu, s, o);
    __shared__ float red[8];
    if ((i & 31) == 0) red[i >> 5] = s;
    __syncthreads();
    if (i < 8) {
        float r2 = red[i];
        #pragma unroll
        for (int o = 4; o; o >>= 1) r2 += __shfl_xor_sync(0xffu, r2, o);
        if (i == 0) g_u[bn] = r2;
    }
}

__global__ void attn_kernel(const float* __restrict__ phis, const float* __restrict__ input,
                            float* __restrict__ out, int t) {
    __shared__ float sat[Nn];
    int b = blockIdx.x, tid = threadIdx.x;
    if (tid < Nn) {
        float mask = phis[(size_t)(b * Nn + t) * Nn + tid];
        float um = g_u[b * Nn + tid] * mask;
        float m = um;
        #pragma unroll
        for (int o = 8; o; o >>= 1) m = fmaxf(m, __shfl_xor_sync(0xffffu, m, o));
        float e = __expf(um - m) * mask;
        float ssum = e;
        #pragma unroll
        for (int o = 8; o; o >>= 1) ssum += __shfl_xor_sync(0xffffu, ssum, o);
        float a = e / ssum;
        sat[tid] = a;
        out[(size_t)(b * Nn + t) * Nn + tid] = a;   // out[b, t, n]
    }
    __syncthreads();
    // inp_step[b, i] = sum_n attn[b,n] * input[b,n,i]
    float s = 0.0f;
    const float* irow = input + (size_t)b * Nn * Ii + tid;
    #pragma unroll
    for (int n = 0; n < Nn; n++) s += sat[n] * irow[n * Ii];
    g_inp[b * Ii + tid] = s;
}

// ---------------- driver ------------------------------------------------------
extern "C" void kernel_launch(void* const* d_in, const int* in_sizes, int n_in,
                              void* d_out, int out_size) {
    const float* input      = (const float*)d_in[0];
    const float* phis       = (const float*)d_in[1];
    const float* init_token = (const float*)d_in[2];
    const float* W1         = (const float*)d_in[3];
    const float* W2         = (const float*)d_in[4];
    const float* v          = (const float*)d_in[5];
    const float* Wih_e      = (const float*)d_in[6];
    const float* Whh_e      = (const float*)d_in[7];
    const float* bih_e      = (const float*)d_in[8];
    const float* bhh_e      = (const float*)d_in[9];
    const float* Wih_d      = (const float*)d_in[10];
    const float* Whh_d      = (const float*)d_in[11];
    const float* bih_d      = (const float*)d_in[12];
    const float* bhh_d      = (const float*)d_in[13];
    float* out = (float*)d_out;

    float *p_gie, *p_henc, *p_w1xe, *p_h, *p_heff, *p_gh, *p_gid, *p_hw2, *p_inp, *p_tg;
    cudaGetSymbolAddress((void**)&p_gie,  g_gie);
    cudaGetSymbolAddress((void**)&p_henc, g_henc);
    cudaGetSymbolAddress((void**)&p_w1xe, g_w1xe);
    cudaGetSymbolAddress((void**)&p_h,    g_h);
    cudaGetSymbolAddress((void**)&p_heff, g_heff);
    cudaGetSymbolAddress((void**)&p_gh,   g_gh);
    cudaGetSymbolAddress((void**)&p_gid,  g_gid);
    cudaGetSymbolAddress((void**)&p_hw2,  g_hw2);
    cudaGetSymbolAddress((void**)&p_inp,  g_inp);
    cudaGetSymbolAddress((void**)&p_tg,   g_tgate);

    const int EW_BLOCKS = (Bb * Hh) / 256;          // 4096

    setup_kernel<<<(Bb * Nn + 255) / 256, 256>>>(phis);
    zero_h_kernel<<<EW_BLOCKS, 256>>>();

    // gi_e = input @ Wih_e^T + bih_e   (16384 x 3072, K=256)
    sgemm<true, false><<<dim3(H3/128, (Bb*Nn)/128), 256>>>(
        input, Wih_e, bih_e, nullptr, p_gie, Bb*Nn, H3, Ii);

    // encoder
    for (int t = 0; t < Nn; t++) {
        // gh = (tg * h) @ Whh_e^T + bhh_e   (1024 x 3072, K=1024), row gate
        sgemm<true, true><<<dim3(H3/128, Bb/128), 256>>>(
            p_h, Whh_e, bhh_e, p_tg + t*Bb, p_gh, Bb, H3, Hh);
        enc_combine<<<EW_BLOCKS, 256>>>(t);
    }

    // W1xe = henc @ W1   (16384 x 1024, K=1024)
    sgemm<false, false><<<dim3(Hh/128, (Bb*Nn)/128), 256>>>(
        p_henc, W1, nullptr, nullptr, p_w1xe, Bb*Nn, Hh, Hh);

    dec_init<<<EW_BLOCKS, 256>>>(init_token);

    // decoder
    for (int t = 0; t < Nn; t++) {
        mix_kernel<<<EW_BLOCKS, 256>>>(init_token, t);
        // gi_d = inp @ Wih_d^T + bih_d   (1024 x 3072, K=256)
        sgemm<true, false><<<dim3(H3/128, Bb/128), 256>>>(
            p_inp, Wih_d, bih_d, nullptr, p_gid, Bb, H3, Ii);
        // gh_d = heff @ Whh_d^T + bhh_d  (1024 x 3072, K=1024)
        sgemm<true, false><<<dim3(H3/128, Bb/128), 256>>>(
            p_heff, Whh_d, bhh_d, nullptr, p_gh, Bb, H3, Hh);
        dec_combine<<<EW_BLOCKS, 256>>>();
        // hW2 = h @ W2   (1024 x 1024, K=1024)
        sgemm<false, false><<<dim3(Hh/128, Bb/128), 256>>>(
            p_h, W2, nullptr, nullptr, p_hw2, Bb, Hh, Hh);
        u_kernel<<<Bb * Nn, 256>>>(v);
        attn_kernel<<<Bb, 256>>>(phis, input, out, t);
    }
}

// round 9
// speedup vs baseline: 2.9514x; 2.9514x over previous
#include <cuda_runtime.h>
#include <cuda_bf16.h>
#include <cstdint>

#define Bb 1024
#define Nn 16
#define Ii 256
#define Hh 1024
#define H3 3072
typedef __nv_bfloat16 bf16;

// ---- fp32 scratch ----
__device__ __align__(256) float g_gie [(size_t)Bb*Nn*H3];
__device__ __align__(256) float g_henc[(size_t)Bb*Nn*Hh];
__device__ __align__(256) float g_w1xe[(size_t)Bb*Nn*Hh];
__device__ __align__(256) float g_h   [Bb*Hh];
__device__ __align__(256) float g_heff[Bb*Hh];
__device__ __align__(256) float g_gh  [Bb*H3];
__device__ __align__(256) float g_gid [Bb*H3];
__device__ __align__(256) float g_hw2 [Bb*Hh];
__device__ __align__(256) float g_inp [Bb*Ii];
__device__ __align__(256) float g_u   [Bb*Nn];
__device__ __align__(256) float g_tgate[Nn*Bb];
__device__ __align__(256) int   g_idx  [Nn*Bb];
// ---- bf16 triple-K operand buffers: A'=[hi|lo|hi], B'=[hi|hi|lo] ----
__device__ __align__(256) bf16 g_inA  [(size_t)Bb*Nn*3*Ii];
__device__ __align__(256) bf16 g_hencA[(size_t)Bb*Nn*3*Hh];
__device__ __align__(256) bf16 g_act  [(size_t)Bb*3*Hh];
__device__ __align__(256) bf16 g_ip   [(size_t)Bb*3*Ii];
__device__ __align__(256) bf16 g_wihe [(size_t)H3*3*Ii];
__device__ __align__(256) bf16 g_whhe [(size_t)H3*3*Hh];
__device__ __align__(256) bf16 g_wihd [(size_t)H3*3*Ii];
__device__ __align__(256) bf16 g_whhd [(size_t)H3*3*Hh];
__device__ __align__(256) bf16 g_w1t  [(size_t)Hh*3*Hh];
__device__ __align__(256) bf16 g_w2t  [(size_t)Hh*3*Hh];

// ---- helpers ----
__device__ __forceinline__ float fsig(float x){ return __fdividef(1.0f, 1.0f + __expf(-x)); }
__device__ __forceinline__ float ftanh(float x){ return 1.0f - __fdividef(2.0f, __expf(2.0f*x)+1.0f); }
__device__ __forceinline__ uint32_t s2u(const void* p){
    uint32_t a; asm("{ .reg .u64 t; cvta.to.shared.u64 t, %1; cvt.u32.u64 %0, t; }":"=r"(a):"l"(p)); return a;
}
__device__ __forceinline__ uint32_t swz(uint32_t o){ return o ^ ((o>>3)&0x70); }
__device__ __forceinline__ void cp16(uint32_t s, const void* g){
    asm volatile("cp.async.cg.shared.global [%0], [%1], 16;"::"r"(s),"l"(g));
}
__device__ __forceinline__ void ldsm4(uint32_t& r0,uint32_t& r1,uint32_t& r2,uint32_t& r3,uint32_t a){
    asm volatile("ldmatrix.sync.aligned.m8n8.x4.shared.b16 {%0,%1,%2,%3},[%4];"
        :"=r"(r0),"=r"(r1),"=r"(r2),"=r"(r3):"r"(a));
}
__device__ __forceinline__ void mma16816(float* c,uint32_t a0,uint32_t a1,uint32_t a2,uint32_t a3,uint32_t b0,uint32_t b1){
    asm volatile("mma.sync.aligned.m16n8k16.row.col.f32.bf16.bf16.f32 {%0,%1,%2,%3},{%4,%5,%6,%7},{%8,%9},{%0,%1,%2,%3};"
        :"+f"(c[0]),"+f"(c[1]),"+f"(c[2]),"+f"(c[3])
        :"r"(a0),"r"(a1),"r"(a2),"r"(a3),"r"(b0),"r"(b1));
}

// ---- bf16 HMMA GEMM: C(M,N) = A'(M,K)·B'(N,K)^T + bias ----
// 128x128 CTA tile, 8 warps (4 row x 2 col), warp tile 32x64, K-chunk 64, 2-stage cp.async.
__global__ void __launch_bounds__(256)
mgemm(const bf16* __restrict__ A, const bf16* __restrict__ B,
      const float* __restrict__ bias, float* __restrict__ C, int N, int K)
{
    extern __shared__ char smem[];
    const uint32_t sb = s2u(smem);             // stage s: A @ s*32768, B @ +16384
    const int tid = threadIdx.x, w = tid>>5, l = tid&31;
    const int bm = blockIdx.y<<7, bn = blockIdx.x<<7;
    const int wy = w&3, wx = w>>2;
    const int NC = K>>6;
    const bf16* Ag = A + (size_t)bm*K;
    const bf16* Bg = B + (size_t)bn*K;

    auto load = [&](int c){
        uint32_t st = sb + (uint32_t)(c&1)*32768u;
        int ko = c<<6;
        #pragma unroll
        for (int i=0;i<4;i++){
            int blk = tid + (i<<8); int row = blk>>3, sg = blk&7;
            uint32_t off = swz((uint32_t)(row*128 + sg*16));
            cp16(st+off,        Ag + (size_t)row*K + ko + sg*8);
            cp16(st+16384u+off, Bg + (size_t)row*K + ko + sg*8);
        }
        asm volatile("cp.async.commit_group;":::"memory");
    };

    float acc[2][8][4];
    #pragma unroll
    for (int i=0;i<2;i++)
        #pragma unroll
        for (int j=0;j<8;j++)
            #pragma unroll
            for (int q=0;q<4;q++) acc[i][j][q] = 0.f;

    const int lr = l & 15, lg = l >> 4;
    load(0);
    for (int c=0;c<NC;c++){
        if (c+1<NC){ load(c+1); asm volatile("cp.async.wait_group 1;":::"memory"); }
        else       {            asm volatile("cp.async.wait_group 0;":::"memory"); }
        __syncthreads();
        uint32_t sA = sb + (uint32_t)(c&1)*32768u;
        uint32_t sB = sA + 16384u;
        #pragma unroll
        for (int s=0;s<4;s++){
            uint32_t af[2][4];
            #pragma unroll
            for (int i=0;i<2;i++){
                uint32_t a = sA + swz((uint32_t)((wy*32 + i*16 + lr)*128 + s*32 + lg*16));
                ldsm4(af[i][0],af[i][1],af[i][2],af[i][3], a);
            }
            #pragma unroll
            for (int j=0;j<4;j++){
                uint32_t b0,b1,b2,b3;
                uint32_t a = sB + swz((uint32_t)((wx*64 + j*16 + lr)*128 + s*32 + lg*16));
                ldsm4(b0,b1,b2,b3, a);
                #pragma unroll
                for (int i=0;i<2;i++){
                    mma16816(acc[i][2*j  ], af[i][0],af[i][1],af[i][2],af[i][3], b0,b2);
                    mma16816(acc[i][2*j+1], af[i][0],af[i][1],af[i][2],af[i][3], b1,b3);
                }
            }
        }
        __syncthreads();
    }

    #pragma unroll
    for (int i=0;i<2;i++){
        int row0 = bm + wy*32 + i*16 + (l>>2);
        #pragma unroll
        for (int j=0;j<8;j++){
            int col = bn + wx*64 + j*8 + (l&3)*2;
            float bx=0.f, by=0.f;
            if (bias){ bx = bias[col]; by = bias[col+1]; }
            float2 v0 = make_float2(acc[i][j][0]+bx, acc[i][j][1]+by);
            float2 v1 = make_float2(acc[i][j][2]+bx, acc[i][j][3]+by);
            *reinterpret_cast<float2*>(C + (size_t)row0*N + col)     = v0;
            *reinterpret_cast<float2*>(C + (size_t)(row0+8)*N + col) = v1;
        }
    }
}

// ---- split kernels ----
// A-side: row -> [hi | lo | hi], optional per-row gate
__global__ void splitA(const float* __restrict__ s, bf16* __restrict__ d, int ksh,
                       const float* __restrict__ gate){
    int i = blockIdx.x*256 + threadIdx.x;
    int K = 1<<ksh, r = i>>ksh, c = i&(K-1);
    float x = s[i];
    if (gate) x *= gate[r];
    bf16 h = __float2bfloat16(x);
    bf16 lo = __float2bfloat16(x - __bfloat162float(h));
    size_t base = (size_t)r*3*K + c;
    d[base] = h; d[base+K] = lo; d[base+2*K] = h;
}
// B-side: row -> [hi | hi | lo]
__global__ void splitB(const float* __restrict__ s, bf16* __restrict__ d, int ksh){
    int i = blockIdx.x*256 + threadIdx.x;
    int K = 1<<ksh, r = i>>ksh, c = i&(K-1);
    float x = s[i];
    bf16 h = __float2bfloat16(x);
    bf16 lo = __float2bfloat16(x - __bfloat162float(h));
    size_t base = (size_t)r*3*K + c;
    d[base] = h; d[base+K] = h; d[base+2*K] = lo;
}
// transpose 1024x1024 W then B-side split
__global__ void tsplitB(const float* __restrict__ W, bf16* __restrict__ d){
    __shared__ float t[32][33];
    int bx = blockIdx.x<<5, by = blockIdx.y<<5, x = threadIdx.x, y = threadIdx.y;
    #pragma unroll
    for (int j=0;j<32;j+=8) t[y+j][x] = W[(size_t)(by+y+j)*Hh + bx+x];
    __syncthreads();
    #pragma unroll
    for (int j=0;j<32;j+=8){
        float v = t[x][y+j];
        bf16 h = __float2bfloat16(v);
        bf16 lo = __float2bfloat16(v - __bfloat162float(h));
        size_t base = (size_t)(bx+y+j)*3*Hh + (by+x);
        d[base] = h; d[base+Hh] = h; d[base+2*Hh] = lo;
    }
}

// ---- small kernels (unchanged from passing R6) ----
__global__ void setup_kernel(const float* __restrict__ phis){
    int id = blockIdx.x*256 + threadIdx.x; if (id >= Bb*Nn) return;
    int b = id>>4, n = id&15;
    const float* prow = phis + (size_t)(b*Nn+n)*Nn;
    float s=0.f;
    #pragma unroll
    for (int k=0;k<Nn;k++) s += prow[k];
    int ns = (int)(s+0.5f);
    g_tgate[n*Bb+b] = (n==0)?1.0f:prow[n-1];
    g_idx[n*Bb+b] = (ns+n-1)&(Nn-1);
}
__global__ void zero_h_kernel(){ g_h[blockIdx.x*256+threadIdx.x] = 0.0f; }
__global__ void enc_combine(int t){
    int id = blockIdx.x*256+threadIdx.x; int b=id>>10, h=id&1023;
    float tg = g_tgate[t*Bb+b];
    float hg = tg*g_h[id];
    const float* gi = g_gie + (size_t)(b*Nn+t)*H3;
    const float* gh = g_gh + (size_t)b*H3;
    float r = fsig(gi[h]+gh[h]);
    float z = fsig(gi[Hh+h]+gh[Hh+h]);
    float g = ftanh(gi[2*Hh+h]+r*gh[2*Hh+h]);
    float hn = (1.0f-z)*g + z*hg;
    g_h[id]=hn; g_henc[(size_t)(b*Nn+t)*Hh+h]=hn;
}
__global__ void dec_init(const float* __restrict__ it){
    int id = blockIdx.x*256+threadIdx.x; int b=id>>10, h=id&1023;
    g_h[id] = g_henc[(size_t)(b*Nn+g_idx[b])*Hh+h];
    if (h<Ii) g_inp[b*Ii+h] = it[h];
}
__global__ void mix_kernel(const float* __restrict__ it, int t){
    int id = blockIdx.x*256+threadIdx.x; int b=id>>10, h=id&1023;
    float tg = g_tgate[t*Bb+b];
    float ih = g_henc[(size_t)(b*Nn+g_idx[t*Bb+b])*Hh+h];
    g_heff[id] = tg*g_h[id] + (1.0f-tg)*ih;
    if (h<Ii){ int j=b*Ii+h; g_inp[j] = tg*g_inp[j] + (1.0f-tg)*it[h]; }
}
__global__ void dec_combine(){
    int id = blockIdx.x*256+threadIdx.x; int b=id>>10, h=id&1023;
    const float* gi = g_gid + (size_t)b*H3;
    const float* gh = g_gh + (size_t)b*H3;
    float r = fsig(gi[h]+gh[h]);
    float z = fsig(gi[Hh+h]+gh[Hh+h]);
    float g = ftanh(gi[2*Hh+h]+r*gh[2*Hh+h]);
    g_h[id] = (1.0f-z)*g + z*g_heff[id];
}
__global__ void u_kernel(const float* __restrict__ v){
    int bn = blockIdx.x; int b = bn>>4; int i = threadIdx.x;
    float4 w  = reinterpret_cast<const float4*>(g_w1xe+(size_t)bn*Hh)[i];
    float4 hw = reinterpret_cast<const float4*>(g_hw2 +(size_t)b *Hh)[i];
    float4 vv = reinterpret_cast<const float4*>(v)[i];
    float s = ftanh(w.x+hw.x)*vv.x + ftanh(w.y+hw.y)*vv.y + ftanh(w.z+hw.z)*vv.z + ftanh(w.w+hw.w)*vv.w;
    #pragma unroll
    for (int o=16;o;o>>=1) s += __shfl_xor_sync(0xffffffffu, s, o);
    __shared__ float red[8];
    if ((i&31)==0) red[i>>5]=s;
    __syncthreads();
    if (i<8){
        float r2 = red[i];
        #pragma unroll
        for (int o=4;o;o>>=1) r2 += __shfl_xor_sync(0xffu, r2, o);
        if (i==0) g_u[bn]=r2;
    }
}
__global__ void attn_kernel(const float* __restrict__ phis, const float* __restrict__ input,
                            float* __restrict__ out, int t){
    __shared__ float sat[Nn];
    int b = blockIdx.x, tid = threadIdx.x;
    if (tid<Nn){
        float mask = phis[(size_t)(b*Nn+t)*Nn+tid];
        float um = g_u[b*Nn+tid]*mask;
        float m = um;
        #pragma unroll
        for (int o=8;o;o>>=1) m = fmaxf(m, __shfl_xor_sync(0xffffu, m, o));
        float e = __expf(um-m)*mask;
        float ss = e;
        #pragma unroll
        for (int o=8;o;o>>=1) ss += __shfl_xor_sync(0xffffu, ss, o);
        float a = e/ss;
        sat[tid]=a;
        out[(size_t)(b*Nn+t)*Nn+tid]=a;
    }
    __syncthreads();
    float s = 0.f;
    const float* irow = input + (size_t)b*Nn*Ii + tid;
    #pragma unroll
    for (int n=0;n<Nn;n++) s += sat[n]*irow[n*Ii];
    g_inp[b*Ii+tid]=s;
}

// ---- driver ----
#define SYM(p,s) cudaGetSymbolAddress((void**)&p, s)
extern "C" void kernel_launch(void* const* d_in, const int* in_sizes, int n_in,
                              void* d_out, int out_size){
    const float* input=(const float*)d_in[0];  const float* phis =(const float*)d_in[1];
    const float* itok =(const float*)d_in[2];  const float* W1   =(const float*)d_in[3];
    const float* W2   =(const float*)d_in[4];  const float* v    =(const float*)d_in[5];
    const float* Wih_e=(const float*)d_in[6];  const float* Whh_e=(const float*)d_in[7];
    const float* bih_e=(const float*)d_in[8];  const float* bhh_e=(const float*)d_in[9];
    const float* Wih_d=(const float*)d_in[10]; const float* Whh_d=(const float*)d_in[11];
    const float* bih_d=(const float*)d_in[12]; const float* bhh_d=(const float*)d_in[13];
    float* out=(float*)d_out;

    float *p_gie,*p_henc,*p_w1xe,*p_h,*p_heff,*p_gh,*p_gid,*p_hw2,*p_inp,*p_tg;
    SYM(p_gie,g_gie); SYM(p_henc,g_henc); SYM(p_w1xe,g_w1xe); SYM(p_h,g_h); SYM(p_heff,g_heff);
    SYM(p_gh,g_gh); SYM(p_gid,g_gid); SYM(p_hw2,g_hw2); SYM(p_inp,g_inp); SYM(p_tg,g_tgate);
    bf16 *inA,*hencA,*act,*ip,*wihe,*whhe,*wihd,*whhd,*w1t,*w2t;
    SYM(inA,g_inA); SYM(hencA,g_hencA); SYM(act,g_act); SYM(ip,g_ip);
    SYM(wihe,g_wihe); SYM(whhe,g_whhe); SYM(wihd,g_wihd); SYM(whhd,g_whhd);
    SYM(w1t,g_w1t); SYM(w2t,g_w2t);

    cudaFuncSetAttribute(mgemm, cudaFuncAttributeMaxDynamicSharedMemorySize, 65536);
    const int EW = (Bb*Hh)/256;

    setup_kernel<<<(Bb*Nn+255)/256,256>>>(phis);
    zero_h_kernel<<<EW,256>>>();

    // one-time operand prep
    splitB<<<(H3*Ii)/256,256>>>(Wih_e, wihe, 8);
    splitB<<<(H3*Hh)/256,256>>>(Whh_e, whhe, 10);
    splitB<<<(H3*Ii)/256,256>>>(Wih_d, wihd, 8);
    splitB<<<(H3*Hh)/256,256>>>(Whh_d, whhd, 10);
    tsplitB<<<dim3(32,32),dim3(32,8)>>>(W1, w1t);
    tsplitB<<<dim3(32,32),dim3(32,8)>>>(W2, w2t);
    splitA<<<(Bb*Nn*Ii)/256,256>>>(input, inA, 8, nullptr);

    // gi_e = input @ Wih_e^T + bih_e   (16384 x 3072, K'=768)
    mgemm<<<dim3(H3/128,(Bb*Nn)/128),256,65536>>>(inA, wihe, bih_e, p_gie, H3, 3*Ii);

    // encoder
    for (int t=0;t<Nn;t++){
        splitA<<<(Bb*Hh)/256,256>>>(p_h, act, 10, p_tg+t*Bb);
        mgemm<<<dim3(H3/128,Bb/128),256,65536>>>(act, whhe, bhh_e, p_gh, H3, 3*Hh);
        enc_combine<<<EW,256>>>(t);
    }

    // W1xe = henc @ W1   (16384 x 1024, K'=3072)
    splitA<<<(Bb*Nn*Hh)/256,256>>>(p_henc, hencA, 10, nullptr);
    mgemm<<<dim3(Hh/128,(Bb*Nn)/128),256,65536>>>(hencA, w1t, nullptr, p_w1xe, Hh, 3*Hh);

    dec_init<<<EW,256>>>(itok);
    // decoder
    for (int t=0;t<Nn;t++){
        mix_kernel<<<EW,256>>>(itok, t);
        splitA<<<(Bb*Hh)/256,256>>>(p_heff, act, 10, nullptr);
        splitA<<<(Bb*Ii)/256,256>>>(p_inp, ip, 8, nullptr);
        mgemm<<<dim3(H3/128,Bb/128),256,65536>>>(ip, wihd, bih_d, p_gid, H3, 3*Ii);
        mgemm<<<dim3(H3/128,Bb/128),256,65536>>>(act, whhd, bhh_d, p_gh, H3, 3*Hh);
        dec_combine<<<EW,256>>>();
        splitA<<<(Bb*Hh)/256,256>>>(p_h, act, 10, nullptr);
        mgemm<<<dim3(Hh/128,Bb/128),256,65536>>>(act, w2t, nullptr, p_hw2, Hh, 3*Hh);
        u_kernel<<<Bb*Nn,256>>>(v);
        attn_kernel<<<Bb,256>>>(phis, input, out, t);
    }
}

// round 10
// speedup vs baseline: 3.3466x; 1.1339x over previous
#include <cuda_runtime.h>
#include <cuda_bf16.h>
#include <cstdint>

#define Bb 1024
#define Nn 16
#define Ii 256
#define Hh 1024
#define H3 3072
typedef __nv_bfloat16 bf16;

// ---- fp32 scratch ----
__device__ __align__(256) float g_gie [(size_t)Bb*Nn*H3];
__device__ __align__(256) float g_henc[(size_t)Bb*Nn*Hh];
__device__ __align__(256) float g_w1xe[(size_t)Bb*Nn*Hh];
__device__ __align__(256) float g_h   [Bb*Hh];
__device__ __align__(256) float g_heff[Bb*Hh];
__device__ __align__(256) float g_gh  [Bb*H3];
__device__ __align__(256) float g_gid [Bb*H3];
__device__ __align__(256) float g_hw2 [Bb*Hh];
__device__ __align__(256) float g_inp [Bb*Ii];
__device__ __align__(256) float g_u   [Bb*Nn];
__device__ __align__(256) float g_tgate[Nn*Bb];
__device__ __align__(256) int   g_idx  [Nn*Bb];
// ---- bf16 triple-K operand buffers: A'=[hi|lo|hi], B'=[hi|hi|lo] ----
__device__ __align__(256) bf16 g_inA  [(size_t)Bb*Nn*3*Ii];
__device__ __align__(256) bf16 g_hencA[(size_t)Bb*Nn*3*Hh];
__device__ __align__(256) bf16 g_act  [(size_t)Bb*3*Hh];
__device__ __align__(256) bf16 g_ip   [(size_t)Bb*3*Ii];
__device__ __align__(256) bf16 g_wihe [(size_t)H3*3*Ii];
__device__ __align__(256) bf16 g_whhe [(size_t)H3*3*Hh];
__device__ __align__(256) bf16 g_wihd [(size_t)H3*3*Ii];
__device__ __align__(256) bf16 g_whhd [(size_t)H3*3*Hh];
__device__ __align__(256) bf16 g_w1t  [(size_t)Hh*3*Hh];
__device__ __align__(256) bf16 g_w2t  [(size_t)Hh*3*Hh];

// ---- helpers ----
__device__ __forceinline__ float fsig(float x){ return __fdividef(1.0f, 1.0f + __expf(-x)); }
__device__ __forceinline__ float ftanh(float x){ return 1.0f - __fdividef(2.0f, __expf(2.0f*x)+1.0f); }
__device__ __forceinline__ uint32_t s2u(const void* p){
    uint32_t a; asm("{ .reg .u64 t; cvta.to.shared.u64 t, %1; cvt.u32.u64 %0, t; }":"=r"(a):"l"(p)); return a;
}
__device__ __forceinline__ uint32_t swz(uint32_t o){ return o ^ ((o>>3)&0x70); }
__device__ __forceinline__ void cp16(uint32_t s, const void* g){
    asm volatile("cp.async.cg.shared.global [%0], [%1], 16;"::"r"(s),"l"(g));
}
__device__ __forceinline__ void ldsm4(uint32_t& r0,uint32_t& r1,uint32_t& r2,uint32_t& r3,uint32_t a){
    asm volatile("ldmatrix.sync.aligned.m8n8.x4.shared.b16 {%0,%1,%2,%3},[%4];"
        :"=r"(r0),"=r"(r1),"=r"(r2),"=r"(r3):"r"(a));
}
__device__ __forceinline__ void mma16816(float* c,uint32_t a0,uint32_t a1,uint32_t a2,uint32_t a3,uint32_t b0,uint32_t b1){
    asm volatile("mma.sync.aligned.m16n8k16.row.col.f32.bf16.bf16.f32 {%0,%1,%2,%3},{%4,%5,%6,%7},{%8,%9},{%0,%1,%2,%3};"
        :"+f"(c[0]),"+f"(c[1]),"+f"(c[2]),"+f"(c[3])
        :"r"(a0),"r"(a1),"r"(a2),"r"(a3),"r"(b0),"r"(b1));
}
__device__ __forceinline__ void split3(float x, bf16* d, size_t base, int K, int c){
    bf16 h = __float2bfloat16(x);
    bf16 lo = __float2bfloat16(x - __bfloat162float(h));
    d[base+c] = h; d[base+K+c] = lo; d[base+2*K+c] = h;
}

// ---- bf16 HMMA GEMM body: C(M,N) = A'(M,K)·B'(N,K)^T + bias ----
// 128xBN CTA tile, 8 warps (4 row x 2 col), warp tile 32x(BN/2), K-chunk 64, 2-stage cp.async.
template<int BN>
__device__ __forceinline__ void gemm_body(
    const bf16* __restrict__ A, const bf16* __restrict__ B,
    const float* __restrict__ bias, float* __restrict__ C,
    int bm, int bn, int N, int K, char* smem)
{
    constexpr int WN  = BN/2;            // cols per warp
    constexpr int STG = 16384 + BN*128;  // bytes per stage
    const uint32_t sb = s2u(smem);
    const int tid = threadIdx.x, w = tid>>5, l = tid&31;
    const int wy = w&3, wx = w>>2;
    const int NC = K>>6;
    const bf16* Ag = A + (size_t)bm*K;
    const bf16* Bg = B + (size_t)bn*K;

    auto load = [&](int c){
        uint32_t st = sb + (uint32_t)(c&1)*STG;
        int ko = c<<6;
        #pragma unroll
        for (int i=0;i<4;i++){
            int blk = tid + (i<<8); int row = blk>>3, sg = blk&7;
            uint32_t off = swz((uint32_t)(row*128 + sg*16));
            cp16(st+off, Ag + (size_t)row*K + ko + sg*8);
        }
        #pragma unroll
        for (int i=0;i<BN/32;i++){
            int blk = tid + (i<<8); int row = blk>>3, sg = blk&7;
            uint32_t off = swz((uint32_t)(row*128 + sg*16));
            cp16(st+16384u+off, Bg + (size_t)row*K + ko + sg*8);
        }
        asm volatile("cp.async.commit_group;":::"memory");
    };

    float acc[2][WN/8][4];
    #pragma unroll
    for (int i=0;i<2;i++)
        #pragma unroll
        for (int j=0;j<WN/8;j++)
            #pragma unroll
            for (int q=0;q<4;q++) acc[i][j][q] = 0.f;

    const int lr = l & 15, lg = l >> 4;
    load(0);
    for (int c=0;c<NC;c++){
        if (c+1<NC){ load(c+1); asm volatile("cp.async.wait_group 1;":::"memory"); }
        else       {            asm volatile("cp.async.wait_group 0;":::"memory"); }
        __syncthreads();
        uint32_t sA = sb + (uint32_t)(c&1)*STG;
        uint32_t sB = sA + 16384u;
        #pragma unroll
        for (int s=0;s<4;s++){
            uint32_t af[2][4];
            #pragma unroll
            for (int i=0;i<2;i++){
                uint32_t a = sA + swz((uint32_t)((wy*32 + i*16 + lr)*128 + s*32 + lg*16));
                ldsm4(af[i][0],af[i][1],af[i][2],af[i][3], a);
            }
            #pragma unroll
            for (int j=0;j<WN/16;j++){
                uint32_t b0,b1,b2,b3;
                uint32_t a = sB + swz((uint32_t)((wx*WN + j*16 + lr)*128 + s*32 + lg*16));
                ldsm4(b0,b1,b2,b3, a);
                #pragma unroll
                for (int i=0;i<2;i++){
                    mma16816(acc[i][2*j  ], af[i][0],af[i][1],af[i][2],af[i][3], b0,b2);
                    mma16816(acc[i][2*j+1], af[i][0],af[i][1],af[i][2],af[i][3], b1,b3);
                }
            }
        }
        __syncthreads();
    }

    #pragma unroll
    for (int i=0;i<2;i++){
        int row0 = bm + wy*32 + i*16 + (l>>2);
        #pragma unroll
        for (int j=0;j<WN/8;j++){
            int col = bn + wx*WN + j*8 + (l&3)*2;
            float bx=0.f, by=0.f;
            if (bias){ bx = bias[col]; by = bias[col+1]; }
            float2 v0 = make_float2(acc[i][j][0]+bx, acc[i][j][1]+by);
            float2 v1 = make_float2(acc[i][j][2]+bx, acc[i][j][3]+by);
            *reinterpret_cast<float2*>(C + (size_t)row0*N + col)     = v0;
            *reinterpret_cast<float2*>(C + (size_t)(row0+8)*N + col) = v1;
        }
    }
}

template<int BN>
__global__ void __launch_bounds__(256, 2)
mgemm(const bf16* __restrict__ A, const bf16* __restrict__ B,
      const float* __restrict__ bias, float* __restrict__ C, int N, int K)
{
    extern __shared__ char smem[];
    gemm_body<BN>(A, B, bias, C, blockIdx.y<<7, blockIdx.x*BN, N, K, smem);
}

// batched pair: z=0 problem0, z=1 problem1 (same N, different A/B/K/bias/C)
__global__ void __launch_bounds__(256, 2)
mgemm_z(const bf16* __restrict__ A0, const bf16* __restrict__ B0,
        const float* __restrict__ b0, float* __restrict__ C0, int K0,
        const bf16* __restrict__ A1, const bf16* __restrict__ B1,
        const float* __restrict__ b1, float* __restrict__ C1, int K1, int N)
{
    extern __shared__ char smem[];
    if (blockIdx.z == 0)
        gemm_body<128>(A0, B0, b0, C0, blockIdx.y<<7, blockIdx.x<<7, N, K0, smem);
    else
        gemm_body<128>(A1, B1, b1, C1, blockIdx.y<<7, blockIdx.x<<7, N, K1, smem);
}

// ---- split kernels (one-time operands) ----
__global__ void splitA(const float* __restrict__ s, bf16* __restrict__ d, int ksh){
    int i = blockIdx.x*256 + threadIdx.x;
    int K = 1<<ksh, r = i>>ksh, c = i&(K-1);
    split3(s[i], d, (size_t)r*3*K, K, c);
}
__global__ void splitB(const float* __restrict__ s, bf16* __restrict__ d, int ksh){
    int i = blockIdx.x*256 + threadIdx.x;
    int K = 1<<ksh, r = i>>ksh, c = i&(K-1);
    float x = s[i];
    bf16 h = __float2bfloat16(x);
    bf16 lo = __float2bfloat16(x - __bfloat162float(h));
    size_t base = (size_t)r*3*K + c;
    d[base] = h; d[base+K] = h; d[base+2*K] = lo;
}
__global__ void tsplitB(const float* __restrict__ W, bf16* __restrict__ d){
    __shared__ float t[32][33];
    int bx = blockIdx.x<<5, by = blockIdx.y<<5, x = threadIdx.x, y = threadIdx.y;
    #pragma unroll
    for (int j=0;j<32;j+=8) t[y+j][x] = W[(size_t)(by+y+j)*Hh + bx+x];
    __syncthreads();
    #pragma unroll
    for (int j=0;j<32;j+=8){
        float v = t[x][y+j];
        bf16 h = __float2bfloat16(v);
        bf16 lo = __float2bfloat16(v - __bfloat162float(h));
        size_t base = (size_t)(bx+y+j)*3*Hh + (by+x);
        d[base] = h; d[base+Hh] = h; d[base+2*Hh] = lo;
    }
}

// ---- fused small kernels ----
__global__ void setup_kernel(const float* __restrict__ phis){
    int id = blockIdx.x*256 + threadIdx.x; if (id >= Bb*Nn) return;
    int b = id>>4, n = id&15;
    const float* prow = phis + (size_t)(b*Nn+n)*Nn;
    float s=0.f;
    #pragma unroll
    for (int k=0;k<Nn;k++) s += prow[k];
    int ns = (int)(s+0.5f);
    g_tgate[n*Bb+b] = (n==0)?1.0f:prow[n-1];
    g_idx[n*Bb+b] = (ns+n-1)&(Nn-1);
}
__global__ void zero_init(){                  // zero g_act (split of tg0*h0=0) and g_h
    int i = blockIdx.x*256+threadIdx.x;       // Bb*3*Hh threads
    g_act[i] = __float2bfloat16(0.f);
    if (i < Bb*Hh) g_h[i] = 0.f;
}
__global__ void enc_combine(int t){           // GRU combine + fused split of next gated h
    int id = blockIdx.x*256+threadIdx.x; int b=id>>10, h=id&1023;
    float tg = g_tgate[t*Bb+b];
    float hg = tg*g_h[id];
    const float* gi = g_gie + (size_t)(b*Nn+t)*H3;
    const float* gh = g_gh + (size_t)b*H3;
    float r = fsig(gi[h]+gh[h]);
    float z = fsig(gi[Hh+h]+gh[Hh+h]);
    float g = ftanh(gi[2*Hh+h]+r*gh[2*Hh+h]);
    float hn = (1.0f-z)*g + z*hg;
    g_h[id]=hn; g_henc[(size_t)(b*Nn+t)*Hh+h]=hn;
    if (t < Nn-1)
        split3(g_tgate[(t+1)*Bb+b]*hn, g_act, (size_t)b*3*Hh, Hh, h);
}
__global__ void dec_init(const float* __restrict__ it){
    int id = blockIdx.x*256+threadIdx.x; int b=id>>10, h=id&1023;
    g_h[id] = g_henc[(size_t)(b*Nn+g_idx[b])*Hh+h];
    if (h<Ii) g_inp[b*Ii+h] = it[h];
}
__global__ void mix_kernel(const float* __restrict__ it, int t){  // mix + split heff & inp
    int id = blockIdx.x*256+threadIdx.x; int b=id>>10, h=id&1023;
    float tg = g_tgate[t*Bb+b];
    float ih = g_henc[(size_t)(b*Nn+g_idx[t*Bb+b])*Hh+h];
    float he = tg*g_h[id] + (1.0f-tg)*ih;
    g_heff[id] = he;
    split3(he, g_act, (size_t)b*3*Hh, Hh, h);
    if (h<Ii){
        int j=b*Ii+h;
        float ni = tg*g_inp[j] + (1.0f-tg)*it[h];
        g_inp[j] = ni;
        split3(ni, g_ip, (size_t)b*3*Ii, Ii, h);
    }
}
__global__ void dec_combine(){                // GRU combine + split of h for hW2
    int id = blockIdx.x*256+threadIdx.x; int b=id>>10, h=id&1023;
    const float* gi = g_gid + (size_t)b*H3;
    const float* gh = g_gh + (size_t)b*H3;
    float r = fsig(gi[h]+gh[h]);
    float z = fsig(gi[Hh+h]+gh[Hh+h]);
    float g = ftanh(gi[2*Hh+h]+r*gh[2*Hh+h]);
    float hn = (1.0f-z)*g + z*g_heff[id];
    g_h[id] = hn;
    split3(hn, g_act, (size_t)b*3*Hh, Hh, h);
}
__global__ void u_kernel(const float* __restrict__ v){
    int bn = blockIdx.x; int b = bn>>4; int i = threadIdx.x;
    float4 w  = reinterpret_cast<const float4*>(g_w1xe+(size_t)bn*Hh)[i];
    float4 hw = reinterpret_cast<const float4*>(g_hw2 +(size_t)b *Hh)[i];
    float4 vv = reinterpret_cast<const float4*>(v)[i];
    float s = ftanh(w.x+hw.x)*vv.x + ftanh(w.y+hw.y)*vv.y + ftanh(w.z+hw.z)*vv.z + ftanh(w.w+hw.w)*vv.w;
    #pragma unroll
    for (int o=16;o;o>>=1) s += __shfl_xor_sync(0xffffffffu, s, o);
    __shared__ float red[8];
    if ((i&31)==0) red[i>>5]=s;
    __syncthreads();
    if (i<8){
        float r2 = red[i];
        #pragma unroll
        for (int o=4;o;o>>=1) r2 += __shfl_xor_sync(0xffu, r2, o);
        if (i==0) g_u[bn]=r2;
    }
}
__global__ void attn_kernel(const float* __restrict__ phis, const float* __restrict__ input,
                            float* __restrict__ out, int t){
    __shared__ float sat[Nn];
    int b = blockIdx.x, tid = threadIdx.x;
    if (tid<Nn){
        float mask = phis[(size_t)(b*Nn+t)*Nn+tid];
        float um = g_u[b*Nn+tid]*mask;
        float m = um;
        #pragma unroll
        for (int o=8;o;o>>=1) m = fmaxf(m, __shfl_xor_sync(0xffffu, m, o));
        float e = __expf(um-m)*mask;
        float ss = e;
        #pragma unroll
        for (int o=8;o;o>>=1) ss += __shfl_xor_sync(0xffffu, ss, o);
        float a = e/ss;
        sat[tid]=a;
        out[(size_t)(b*Nn+t)*Nn+tid]=a;
    }
    __syncthreads();
    float s = 0.f;
    const float* irow = input + (size_t)b*Nn*Ii + tid;
    #pragma unroll
    for (int n=0;n<Nn;n++) s += sat[n]*irow[n*Ii];
    g_inp[b*Ii+tid]=s;
}

// ---- driver ----
#define SYM(p,s) cudaGetSymbolAddress((void**)&p, s)
extern "C" void kernel_launch(void* const* d_in, const int* in_sizes, int n_in,
                              void* d_out, int out_size){
    const float* input=(const float*)d_in[0];  const float* phis =(const float*)d_in[1];
    const float* itok =(const float*)d_in[2];  const float* W1   =(const float*)d_in[3];
    const float* W2   =(const float*)d_in[4];  const float* v    =(const float*)d_in[5];
    const float* Wih_e=(const float*)d_in[6];  const float* Whh_e=(const float*)d_in[7];
    const float* bih_e=(const float*)d_in[8];  const float* bhh_e=(const float*)d_in[9];
    const float* Wih_d=(const float*)d_in[10]; const float* Whh_d=(const float*)d_in[11];
    const float* bih_d=(const float*)d_in[12]; const float* bhh_d=(const float*)d_in[13];
    float* out=(float*)d_out;

    float *p_gie,*p_henc,*p_w1xe,*p_gh,*p_gid,*p_hw2;
    SYM(p_gie,g_gie); SYM(p_henc,g_henc); SYM(p_w1xe,g_w1xe);
    SYM(p_gh,g_gh); SYM(p_gid,g_gid); SYM(p_hw2,g_hw2);
    bf16 *inA,*hencA,*act,*ip,*wihe,*whhe,*wihd,*whhd,*w1t,*w2t;
    SYM(inA,g_inA); SYM(hencA,g_hencA); SYM(act,g_act); SYM(ip,g_ip);
    SYM(wihe,g_wihe); SYM(whhe,g_whhe); SYM(wihd,g_wihd); SYM(whhd,g_whhd);
    SYM(w1t,g_w1t); SYM(w2t,g_w2t);

    const int SM128 = 2*(16384 + 128*128);   // 65536
    const int SM64  = 2*(16384 + 64*128);    // 49152
    cudaFuncSetAttribute(mgemm<128>, cudaFuncAttributeMaxDynamicSharedMemorySize, SM128);
    cudaFuncSetAttribute(mgemm<64>,  cudaFuncAttributeMaxDynamicSharedMemorySize, SM64);
    cudaFuncSetAttribute(mgemm_z,    cudaFuncAttributeMaxDynamicSharedMemorySize, SM128);
    const int EW = (Bb*Hh)/256;

    setup_kernel<<<(Bb*Nn+255)/256,256>>>(phis);
    zero_init<<<(Bb*3*Hh)/256,256>>>();

    // one-time operand prep
    splitB<<<(H3*Ii)/256,256>>>(Wih_e, wihe, 8);
    splitB<<<(H3*Hh)/256,256>>>(Whh_e, whhe, 10);
    splitB<<<(H3*Ii)/256,256>>>(Wih_d, wihd, 8);
    splitB<<<(H3*Hh)/256,256>>>(Whh_d, whhd, 10);
    tsplitB<<<dim3(32,32),dim3(32,8)>>>(W1, w1t);
    tsplitB<<<dim3(32,32),dim3(32,8)>>>(W2, w2t);
    splitA<<<(Bb*Nn*Ii)/256,256>>>(input, inA, 8);

    // gi_e = input @ Wih_e^T + bih_e   (16384 x 3072, K'=768)
    mgemm<128><<<dim3(H3/128,(Bb*Nn)/128),256,SM128>>>(inA, wihe, bih_e, p_gie, H3, 3*Ii);

    // encoder (act pre-seeded with split(tg*h); enc_combine writes next act)
    for (int t=0;t<Nn;t++){
        mgemm<128><<<dim3(H3/128,Bb/128),256,SM128>>>(act, whhe, bhh_e, p_gh, H3, 3*Hh);
        enc_combine<<<EW,256>>>(t);
    }

    // W1xe = henc @ W1   (16384 x 1024, K'=3072)
    splitA<<<(Bb*Nn*Hh)/256,256>>>(p_henc, hencA, 10);
    mgemm<128><<<dim3(Hh/128,(Bb*Nn)/128),256,SM128>>>(hencA, w1t, nullptr, p_w1xe, Hh, 3*Hh);

    dec_init<<<EW,256>>>(itok);
    // decoder
    for (int t=0;t<Nn;t++){
        mix_kernel<<<EW,256>>>(itok, t);
        mgemm_z<<<dim3(H3/128,Bb/128,2),256,SM128>>>(
            ip,  wihd, bih_d, p_gid, 3*Ii,
            act, whhd, bhh_d, p_gh,  3*Hh, H3);
        dec_combine<<<EW,256>>>();
        mgemm<64><<<dim3(Hh/64,Bb/128),256,SM64>>>(act, w2t, nullptr, p_hw2, Hh, 3*Hh);
        u_kernel<<<Bb*Nn,256>>>(v);
        attn_kernel<<<Bb,256>>>(phis, input, out, t);
    }
}

// round 11
// speedup vs baseline: 3.3836x; 1.0110x over previous
#include <cuda_runtime.h>
#include <cuda_bf16.h>
#include <cstdint>

#define Bb 1024
#define Nn 16
#define Ii 256
#define Hh 1024
#define H3 3072
typedef __nv_bfloat16 bf16;

// ---- fp32 scratch ----
__device__ __align__(256) float g_gie [(size_t)Bb*Nn*H3];
__device__ __align__(256) float g_henc[(size_t)Bb*Nn*Hh];
__device__ __align__(256) float g_w1xe[(size_t)Bb*Nn*Hh];
__device__ __align__(256) float g_h   [Bb*Hh];
__device__ __align__(256) float g_heff[Bb*Hh];
__device__ __align__(256) float g_gh  [Bb*H3];
__device__ __align__(256) float g_gid [Bb*H3];
__device__ __align__(256) float g_hw2 [Bb*Hh];
__device__ __align__(256) float g_inp [Bb*Ii];
__device__ __align__(256) float g_tgate[Nn*Bb];
__device__ __align__(256) int   g_idx  [Nn*Bb];
// ---- bf16 triple-K operand buffers: A'=[hi|lo|hi], B'=[hi|hi|lo] ----
__device__ __align__(256) bf16 g_inA  [(size_t)Bb*Nn*3*Ii];
__device__ __align__(256) bf16 g_hencA[(size_t)Bb*Nn*3*Hh];
__device__ __align__(256) bf16 g_act  [(size_t)Bb*3*Hh];
__device__ __align__(256) bf16 g_ip   [(size_t)Bb*3*Ii];
__device__ __align__(256) bf16 g_wihe [(size_t)H3*3*Ii];
__device__ __align__(256) bf16 g_whhe [(size_t)H3*3*Hh];
__device__ __align__(256) bf16 g_wihd [(size_t)H3*3*Ii];
__device__ __align__(256) bf16 g_whhd [(size_t)H3*3*Hh];
__device__ __align__(256) bf16 g_w1t  [(size_t)Hh*3*Hh];
__device__ __align__(256) bf16 g_w2t  [(size_t)Hh*3*Hh];

// ---- helpers ----
__device__ __forceinline__ float fsig(float x){ return __fdividef(1.0f, 1.0f + __expf(-x)); }
__device__ __forceinline__ float ftanh(float x){ return 1.0f - __fdividef(2.0f, __expf(2.0f*x)+1.0f); }
__device__ __forceinline__ uint32_t s2u(const void* p){
    uint32_t a; asm("{ .reg .u64 t; cvta.to.shared.u64 t, %1; cvt.u32.u64 %0, t; }":"=r"(a):"l"(p)); return a;
}
__device__ __forceinline__ uint32_t swz(uint32_t o){ return o ^ ((o>>3)&0x70); }
__device__ __forceinline__ void cp16(uint32_t s, const void* g){
    asm volatile("cp.async.cg.shared.global [%0], [%1], 16;"::"r"(s),"l"(g));
}
__device__ __forceinline__ void ldsm4(uint32_t& r0,uint32_t& r1,uint32_t& r2,uint32_t& r3,uint32_t a){
    asm volatile("ldmatrix.sync.aligned.m8n8.x4.shared.b16 {%0,%1,%2,%3},[%4];"
        :"=r"(r0),"=r"(r1),"=r"(r2),"=r"(r3):"r"(a));
}
__device__ __forceinline__ void mma16816(float* c,uint32_t a0,uint32_t a1,uint32_t a2,uint32_t a3,uint32_t b0,uint32_t b1){
    asm volatile("mma.sync.aligned.m16n8k16.row.col.f32.bf16.bf16.f32 {%0,%1,%2,%3},{%4,%5,%6,%7},{%8,%9},{%0,%1,%2,%3};"
        :"+f"(c[0]),"+f"(c[1]),"+f"(c[2]),"+f"(c[3])
        :"r"(a0),"r"(a1),"r"(a2),"r"(a3),"r"(b0),"r"(b1));
}
__device__ __forceinline__ void split3(float x, bf16* d, size_t base, int K, int c){
    bf16 h = __float2bfloat16(x);
    bf16 lo = __float2bfloat16(x - __bfloat162float(h));
    d[base+c] = h; d[base+K+c] = lo; d[base+2*K+c] = h;
}

// ---- bf16 HMMA GEMM body: C(M,N) = A'(M,K)·B'(N,K)^T + bias ----
// 128xBN CTA tile, 8 warps (4x2), warp tile 32x(BN/2), K-chunk 64,
// 3-stage cp.async pipeline, ONE __syncthreads per chunk.
template<int BN>
__device__ __forceinline__ void gemm_body(
    const bf16* __restrict__ A, const bf16* __restrict__ B,
    const float* __restrict__ bias, float* __restrict__ C,
    int bm, int bn, int N, int K, char* smem)
{
    constexpr int WN  = BN/2;
    constexpr int STG = 16384 + BN*128;
    const uint32_t sb = s2u(smem);
    const int tid = threadIdx.x, w = tid>>5, l = tid&31;
    const int wy = w&3, wx = w>>2;
    const int NC = K>>6;
    const bf16* Ag = A + (size_t)bm*K;
    const bf16* Bg = B + (size_t)bn*K;

    auto load = [&](int c){
        uint32_t st = sb + (uint32_t)(c%3)*STG;
        int ko = c<<6;
        #pragma unroll
        for (int i=0;i<4;i++){
            int blk = tid + (i<<8); int row = blk>>3, sg = blk&7;
            uint32_t off = swz((uint32_t)(row*128 + sg*16));
            cp16(st+off, Ag + (size_t)row*K + ko + sg*8);
        }
        #pragma unroll
        for (int i=0;i<BN/32;i++){
            int blk = tid + (i<<8); int row = blk>>3, sg = blk&7;
            uint32_t off = swz((uint32_t)(row*128 + sg*16));
            cp16(st+16384u+off, Bg + (size_t)row*K + ko + sg*8);
        }
        asm volatile("cp.async.commit_group;":::"memory");
    };

    float acc[2][WN/8][4];
    #pragma unroll
    for (int i=0;i<2;i++)
        #pragma unroll
        for (int j=0;j<WN/8;j++)
            #pragma unroll
            for (int q=0;q<4;q++) acc[i][j][q] = 0.f;

    const int lr = l & 15, lg = l >> 4;
    load(0); load(1);
    for (int c=0;c<NC;c++){
        if (c+1<NC) asm volatile("cp.async.wait_group 1;":::"memory");
        else        asm volatile("cp.async.wait_group 0;":::"memory");
        __syncthreads();
        if (c+2<NC) load(c+2);
        uint32_t sA = sb + (uint32_t)(c%3)*STG;
        uint32_t sB = sA + 16384u;
        #pragma unroll
        for (int s=0;s<4;s++){
            uint32_t af[2][4];
            #pragma unroll
            for (int i=0;i<2;i++){
                uint32_t a = sA + swz((uint32_t)((wy*32 + i*16 + lr)*128 + s*32 + lg*16));
                ldsm4(af[i][0],af[i][1],af[i][2],af[i][3], a);
            }
            #pragma unroll
            for (int j=0;j<WN/16;j++){
                uint32_t b0,b1,b2,b3;
                uint32_t a = sB + swz((uint32_t)((wx*WN + j*16 + lr)*128 + s*32 + lg*16));
                ldsm4(b0,b1,b2,b3, a);
                #pragma unroll
                for (int i=0;i<2;i++){
                    mma16816(acc[i][2*j  ], af[i][0],af[i][1],af[i][2],af[i][3], b0,b2);
                    mma16816(acc[i][2*j+1], af[i][0],af[i][1],af[i][2],af[i][3], b1,b3);
                }
            }
        }
    }

    #pragma unroll
    for (int i=0;i<2;i++){
        int row0 = bm + wy*32 + i*16 + (l>>2);
        #pragma unroll
        for (int j=0;j<WN/8;j++){
            int col = bn + wx*WN + j*8 + (l&3)*2;
            float bx=0.f, by=0.f;
            if (bias){ bx = bias[col]; by = bias[col+1]; }
            float2 v0 = make_float2(acc[i][j][0]+bx, acc[i][j][1]+by);
            float2 v1 = make_float2(acc[i][j][2]+bx, acc[i][j][3]+by);
            *reinterpret_cast<float2*>(C + (size_t)row0*N + col)     = v0;
            *reinterpret_cast<float2*>(C + (size_t)(row0+8)*N + col) = v1;
        }
    }
}

template<int BN>
__global__ void __launch_bounds__(256, 2)
mgemm(const bf16* __restrict__ A, const bf16* __restrict__ B,
      const float* __restrict__ bias, float* __restrict__ C, int N, int K)
{
    extern __shared__ char smem[];
    gemm_body<BN>(A, B, bias, C, blockIdx.y<<7, blockIdx.x*BN, N, K, smem);
}

__global__ void __launch_bounds__(256, 2)
mgemm_z(const bf16* __restrict__ A0, const bf16* __restrict__ B0,
        const float* __restrict__ b0, float* __restrict__ C0, int K0,
        const bf16* __restrict__ A1, const bf16* __restrict__ B1,
        const float* __restrict__ b1, float* __restrict__ C1, int K1, int N)
{
    extern __shared__ char smem[];
    if (blockIdx.z == 0)
        gemm_body<128>(A0, B0, b0, C0, blockIdx.y<<7, blockIdx.x<<7, N, K0, smem);
    else
        gemm_body<128>(A1, B1, b1, C1, blockIdx.y<<7, blockIdx.x<<7, N, K1, smem);
}

// ---- split kernels (one-time operands) ----
__global__ void splitA(const float* __restrict__ s, bf16* __restrict__ d, int ksh){
    int i = blockIdx.x*256 + threadIdx.x;
    int K = 1<<ksh, r = i>>ksh, c = i&(K-1);
    split3(s[i], d, (size_t)r*3*K, K, c);
}
__global__ void splitB(const float* __restrict__ s, bf16* __restrict__ d, int ksh){
    int i = blockIdx.x*256 + threadIdx.x;
    int K = 1<<ksh, r = i>>ksh, c = i&(K-1);
    float x = s[i];
    bf16 h = __float2bfloat16(x);
    bf16 lo = __float2bfloat16(x - __bfloat162float(h));
    size_t base = (size_t)r*3*K + c;
    d[base] = h; d[base+K] = h; d[base+2*K] = lo;
}
__global__ void tsplitB(const float* __restrict__ W, bf16* __restrict__ d){
    __shared__ float t[32][33];
    int bx = blockIdx.x<<5, by = blockIdx.y<<5, x = threadIdx.x, y = threadIdx.y;
    #pragma unroll
    for (int j=0;j<32;j+=8) t[y+j][x] = W[(size_t)(by+y+j)*Hh + bx+x];
    __syncthreads();
    #pragma unroll
    for (int j=0;j<32;j+=8){
        float v = t[x][y+j];
        bf16 h = __float2bfloat16(v);
        bf16 lo = __float2bfloat16(v - __bfloat162float(h));
        size_t base = (size_t)(bx+y+j)*3*Hh + (by+x);
        d[base] = h; d[base+Hh] = h; d[base+2*Hh] = lo;
    }
}

// ---- fused small kernels ----
__global__ void setup_kernel(const float* __restrict__ phis){
    int id = blockIdx.x*256 + threadIdx.x; if (id >= Bb*Nn) return;
    int b = id>>4, n = id&15;
    const float* prow = phis + (size_t)(b*Nn+n)*Nn;
    float s=0.f;
    #pragma unroll
    for (int k=0;k<Nn;k++) s += prow[k];
    int ns = (int)(s+0.5f);
    g_tgate[n*Bb+b] = (n==0)?1.0f:prow[n-1];
    g_idx[n*Bb+b] = (ns+n-1)&(Nn-1);
}
__global__ void zero_init(){
    int i = blockIdx.x*256+threadIdx.x;
    g_act[i] = __float2bfloat16(0.f);
    if (i < Bb*Hh) g_h[i] = 0.f;
}
__global__ void enc_combine(int t){
    int id = blockIdx.x*256+threadIdx.x; int b=id>>10, h=id&1023;
    float tg = g_tgate[t*Bb+b];
    float hg = tg*g_h[id];
    const float* gi = g_gie + (size_t)(b*Nn+t)*H3;
    const float* gh = g_gh + (size_t)b*H3;
    float r = fsig(gi[h]+gh[h]);
    float z = fsig(gi[Hh+h]+gh[Hh+h]);
    float g = ftanh(gi[2*Hh+h]+r*gh[2*Hh+h]);
    float hn = (1.0f-z)*g + z*hg;
    g_h[id]=hn; g_henc[(size_t)(b*Nn+t)*Hh+h]=hn;
    if (t < Nn-1)
        split3(g_tgate[(t+1)*Bb+b]*hn, g_act, (size_t)b*3*Hh, Hh, h);
}
__global__ void dec_init(const float* __restrict__ it){
    int id = blockIdx.x*256+threadIdx.x; int b=id>>10, h=id&1023;
    g_h[id] = g_henc[(size_t)(b*Nn+g_idx[b])*Hh+h];
    if (h<Ii) g_inp[b*Ii+h] = it[h];
}
__global__ void mix_kernel(const float* __restrict__ it, int t){
    int id = blockIdx.x*256+threadIdx.x; int b=id>>10, h=id&1023;
    float tg = g_tgate[t*Bb+b];
    float ih = g_henc[(size_t)(b*Nn+g_idx[t*Bb+b])*Hh+h];
    float he = tg*g_h[id] + (1.0f-tg)*ih;
    g_heff[id] = he;
    split3(he, g_act, (size_t)b*3*Hh, Hh, h);
    if (h<Ii){
        int j=b*Ii+h;
        float ni = tg*g_inp[j] + (1.0f-tg)*it[h];
        g_inp[j] = ni;
        split3(ni, g_ip, (size_t)b*3*Ii, Ii, h);
    }
}
__global__ void dec_combine(){
    int id = blockIdx.x*256+threadIdx.x; int b=id>>10, h=id&1023;
    const float* gi = g_gid + (size_t)b*H3;
    const float* gh = g_gh + (size_t)b*H3;
    float r = fsig(gi[h]+gh[h]);
    float z = fsig(gi[Hh+h]+gh[Hh+h]);
    float g = ftanh(gi[2*Hh+h]+r*gh[2*Hh+h]);
    float hn = (1.0f-z)*g + z*g_heff[id];
    g_h[id] = hn;
    split3(hn, g_act, (size_t)b*3*Hh, Hh, h);
}
// fused: u logits (8 warps x 2 n) + masked softmax + context matvec
__global__ void attn_fused(const float* __restrict__ v, const float* __restrict__ phis,
                           const float* __restrict__ input, float* __restrict__ out, int t){
    __shared__ float su[Nn];
    __shared__ float sat[Nn];
    int b = blockIdx.x, tid = threadIdx.x, w = tid>>5, l = tid&31;
    const float4* hrow = reinterpret_cast<const float4*>(g_hw2 + (size_t)b*Hh);
    const float4* vv4  = reinterpret_cast<const float4*>(v);
    #pragma unroll
    for (int nn=0; nn<2; nn++){
        int n = w + nn*8;
        const float4* wrow = reinterpret_cast<const float4*>(g_w1xe + (size_t)(b*Nn+n)*Hh);
        float s = 0.f;
        #pragma unroll
        for (int i=l; i<256; i+=32){
            float4 a = wrow[i], h4 = hrow[i], vv = vv4[i];
            s += ftanh(a.x+h4.x)*vv.x + ftanh(a.y+h4.y)*vv.y
               + ftanh(a.z+h4.z)*vv.z + ftanh(a.w+h4.w)*vv.w;
        }
        #pragma unroll
        for (int o=16;o;o>>=1) s += __shfl_xor_sync(0xffffffffu, s, o);
        if (l==0) su[n] = s;
    }
    __syncthreads();
    if (tid<Nn){
        float mask = phis[(size_t)(b*Nn+t)*Nn+tid];
        float um = su[tid]*mask;
        float m = um;
        #pragma unroll
        for (int o=8;o;o>>=1) m = fmaxf(m, __shfl_xor_sync(0xffffu, m, o));
        float e = __expf(um-m)*mask;
        float ss = e;
        #pragma unroll
        for (int o=8;o;o>>=1) ss += __shfl_xor_sync(0xffffu, ss, o);
        float a = e/ss;
        sat[tid]=a;
        out[(size_t)(b*Nn+t)*Nn+tid]=a;
    }
    __syncthreads();
    float s = 0.f;
    const float* irow = input + (size_t)b*Nn*Ii + tid;
    #pragma unroll
    for (int n=0;n<Nn;n++) s += sat[n]*irow[n*Ii];
    g_inp[b*Ii+tid]=s;
}

// ---- driver ----
#define SYM(p,s) cudaGetSymbolAddress((void**)&p, s)
extern "C" void kernel_launch(void* const* d_in, const int* in_sizes, int n_in,
                              void* d_out, int out_size){
    const float* input=(const float*)d_in[0];  const float* phis =(const float*)d_in[1];
    const float* itok =(const float*)d_in[2];  const float* W1   =(const float*)d_in[3];
    const float* W2   =(const float*)d_in[4];  const float* v    =(const float*)d_in[5];
    const float* Wih_e=(const float*)d_in[6];  const float* Whh_e=(const float*)d_in[7];
    const float* bih_e=(const float*)d_in[8];  const float* bhh_e=(const float*)d_in[9];
    const float* Wih_d=(const float*)d_in[10]; const float* Whh_d=(const float*)d_in[11];
    const float* bih_d=(const float*)d_in[12]; const float* bhh_d=(const float*)d_in[13];
    float* out=(float*)d_out;

    float *p_gie,*p_henc,*p_w1xe,*p_gh,*p_gid,*p_hw2;
    SYM(p_gie,g_gie); SYM(p_henc,g_henc); SYM(p_w1xe,g_w1xe);
    SYM(p_gh,g_gh); SYM(p_gid,g_gid); SYM(p_hw2,g_hw2);
    bf16 *inA,*hencA,*act,*ip,*wihe,*whhe,*wihd,*whhd,*w1t,*w2t;
    SYM(inA,g_inA); SYM(hencA,g_hencA); SYM(act,g_act); SYM(ip,g_ip);
    SYM(wihe,g_wihe); SYM(whhe,g_whhe); SYM(wihd,g_wihd); SYM(whhd,g_whhd);
    SYM(w1t,g_w1t); SYM(w2t,g_w2t);

    const int SM128 = 3*(16384 + 128*128);   // 98304
    const int SM64  = 3*(16384 + 64*128);    // 73728
    cudaFuncSetAttribute(mgemm<128>, cudaFuncAttributeMaxDynamicSharedMemorySize, SM128);
    cudaFuncSetAttribute(mgemm<64>,  cudaFuncAttributeMaxDynamicSharedMemorySize, SM64);
    cudaFuncSetAttribute(mgemm_z,    cudaFuncAttributeMaxDynamicSharedMemorySize, SM128);
    const int EW = (Bb*Hh)/256;

    // prologue ordered so launch #6 (ncu -s 5 -c 1) is an mgemm
    setup_kernel<<<(Bb*Nn+255)/256,256>>>(phis);                 // 1
    zero_init<<<(Bb*3*Hh)/256,256>>>();                          // 2
    splitB<<<(H3*Ii)/256,256>>>(Wih_e, wihe, 8);                 // 3
    splitB<<<(H3*Hh)/256,256>>>(Whh_e, whhe, 10);                // 4
    splitA<<<(Bb*Nn*Ii)/256,256>>>(input, inA, 8);               // 5
    mgemm<128><<<dim3(H3/128,(Bb*Nn)/128),256,SM128>>>(          // 6 <- profiled
        inA, wihe, bih_e, p_gie, H3, 3*Ii);
    splitB<<<(H3*Ii)/256,256>>>(Wih_d, wihd, 8);
    splitB<<<(H3*Hh)/256,256>>>(Whh_d, whhd, 10);
    tsplitB<<<dim3(32,32),dim3(32,8)>>>(W1, w1t);
    tsplitB<<<dim3(32,32),dim3(32,8)>>>(W2, w2t);

    // encoder
    for (int t=0;t<Nn;t++){
        mgemm<128><<<dim3(H3/128,Bb/128),256,SM128>>>(act, whhe, bhh_e, p_gh, H3, 3*Hh);
        enc_combine<<<EW,256>>>(t);
    }

    // W1xe = henc @ W1
    splitA<<<(Bb*Nn*Hh)/256,256>>>(p_henc, hencA, 10);
    mgemm<128><<<dim3(Hh/128,(Bb*Nn)/128),256,SM128>>>(hencA, w1t, nullptr, p_w1xe, Hh, 3*Hh);

    dec_init<<<EW,256>>>(itok);
    // decoder
    for (int t=0;t<Nn;t++){
        mix_kernel<<<EW,256>>>(itok, t);
        mgemm_z<<<dim3(H3/128,Bb/128,2),256,SM128>>>(
            ip,  wihd, bih_d, p_gid, 3*Ii,
            act, whhd, bhh_d, p_gh,  3*Hh, H3);
        dec_combine<<<EW,256>>>();
        mgemm<64><<<dim3(Hh/64,Bb/128),256,SM64>>>(act, w2t, nullptr, p_hw2, Hh, 3*Hh);
        attn_fused<<<Bb,256>>>(v, phis, input, out, t);
    }
}

// round 12
// speedup vs baseline: 3.5376x; 1.0455x over previous
#include <cuda_runtime.h>
#include <cuda_bf16.h>
#include <cstdint>

#define Bb 1024
#define Nn 16
#define Ii 256
#define Hh 1024
#define H3 3072
typedef __nv_bfloat16 bf16;

// ---- fp32 scratch ----
__device__ __align__(256) float g_gie [(size_t)Bb*Nn*H3];
__device__ __align__(256) float g_henc[(size_t)Bb*Nn*Hh];
__device__ __align__(256) float g_w1xe[(size_t)Bb*Nn*Hh];
__device__ __align__(256) float g_h   [Bb*Hh];
__device__ __align__(256) float g_heff[Bb*Hh];
__device__ __align__(256) float g_gh  [Bb*H3];
__device__ __align__(256) float g_gid [Bb*H3];
__device__ __align__(256) float g_hw2 [Bb*Hh];
__device__ __align__(256) float g_tgate[Nn*Bb];
__device__ __align__(256) int   g_idx  [Nn*Bb];
// ---- bf16 triple-K operand buffers: A'=[hi|lo|hi], B'=[hi|hi|lo] ----
__device__ __align__(256) bf16 g_inA  [(size_t)Bb*Nn*3*Ii];
__device__ __align__(256) bf16 g_hencA[(size_t)Bb*Nn*3*Hh];
__device__ __align__(256) bf16 g_act  [(size_t)Bb*3*Hh];   // split(heff(t))
__device__ __align__(256) bf16 g_actH [(size_t)Bb*3*Hh];   // split(h(t)) for hW2
__device__ __align__(256) bf16 g_ip   [(size_t)Bb*3*Ii];
__device__ __align__(256) bf16 g_wihe [(size_t)H3*3*Ii];
__device__ __align__(256) bf16 g_whhe [(size_t)H3*3*Hh];
__device__ __align__(256) bf16 g_wihd [(size_t)H3*3*Ii];
__device__ __align__(256) bf16 g_whhd [(size_t)H3*3*Hh];
__device__ __align__(256) bf16 g_w1t  [(size_t)Hh*3*Hh];
__device__ __align__(256) bf16 g_w2t  [(size_t)Hh*3*Hh];

// ---- helpers ----
__device__ __forceinline__ float fsig(float x){ return __fdividef(1.0f, 1.0f + __expf(-x)); }
__device__ __forceinline__ float ftanh(float x){ return 1.0f - __fdividef(2.0f, __expf(2.0f*x)+1.0f); }
__device__ __forceinline__ uint32_t s2u(const void* p){
    uint32_t a; asm("{ .reg .u64 t; cvta.to.shared.u64 t, %1; cvt.u32.u64 %0, t; }":"=r"(a):"l"(p)); return a;
}
__device__ __forceinline__ uint32_t swz(uint32_t o){ return o ^ ((o>>3)&0x70); }
__device__ __forceinline__ void cp16(uint32_t s, const void* g){
    asm volatile("cp.async.cg.shared.global [%0], [%1], 16;"::"r"(s),"l"(g));
}
__device__ __forceinline__ void ldsm4(uint32_t& r0,uint32_t& r1,uint32_t& r2,uint32_t& r3,uint32_t a){
    asm volatile("ldmatrix.sync.aligned.m8n8.x4.shared.b16 {%0,%1,%2,%3},[%4];"
        :"=r"(r0),"=r"(r1),"=r"(r2),"=r"(r3):"r"(a));
}
__device__ __forceinline__ void mma16816(float* c,uint32_t a0,uint32_t a1,uint32_t a2,uint32_t a3,uint32_t b0,uint32_t b1){
    asm volatile("mma.sync.aligned.m16n8k16.row.col.f32.bf16.bf16.f32 {%0,%1,%2,%3},{%4,%5,%6,%7},{%8,%9},{%0,%1,%2,%3};"
        :"+f"(c[0]),"+f"(c[1]),"+f"(c[2]),"+f"(c[3])
        :"r"(a0),"r"(a1),"r"(a2),"r"(a3),"r"(b0),"r"(b1));
}
__device__ __forceinline__ void split3(float x, bf16* d, size_t base, int K, int c){
    bf16 h = __float2bfloat16(x);
    bf16 lo = __float2bfloat16(x - __bfloat162float(h));
    d[base+c] = h; d[base+K+c] = lo; d[base+2*K+c] = h;
}

// ---- bf16 HMMA GEMM body: C(M,N) = A'(M,K)·B'(N,K)^T + bias ----
// 128xBN CTA tile, 8 warps (4x2), warp tile 32x(BN/2), K-chunk 64, NS-stage cp.async.
template<int BN, int NS>
__device__ __forceinline__ void gemm_body(
    const bf16* __restrict__ A, const bf16* __restrict__ B,
    const float* __restrict__ bias, float* __restrict__ C,
    int bm, int bn, int N, int K, char* smem)
{
    constexpr int WN  = BN/2;
    constexpr int STG = 16384 + BN*128;
    const uint32_t sb = s2u(smem);
    const int tid = threadIdx.x, w = tid>>5, l = tid&31;
    const int wy = w&3, wx = w>>2;
    const int NC = K>>6;
    const bf16* Ag = A + (size_t)bm*K;
    const bf16* Bg = B + (size_t)bn*K;

    auto load = [&](int c){
        uint32_t st = sb + (uint32_t)(c%NS)*STG;
        int ko = c<<6;
        #pragma unroll
        for (int i=0;i<4;i++){
            int blk = tid + (i<<8); int row = blk>>3, sg = blk&7;
            uint32_t off = swz((uint32_t)(row*128 + sg*16));
            cp16(st+off, Ag + (size_t)row*K + ko + sg*8);
        }
        #pragma unroll
        for (int i=0;i<BN/32;i++){
            int blk = tid + (i<<8); int row = blk>>3, sg = blk&7;
            uint32_t off = swz((uint32_t)(row*128 + sg*16));
            cp16(st+16384u+off, Bg + (size_t)row*K + ko + sg*8);
        }
        asm volatile("cp.async.commit_group;":::"memory");
    };

    float acc[2][WN/8][4];
    #pragma unroll
    for (int i=0;i<2;i++)
        #pragma unroll
        for (int j=0;j<WN/8;j++)
            #pragma unroll
            for (int q=0;q<4;q++) acc[i][j][q] = 0.f;

    const int lr = l & 15, lg = l >> 4;
    #pragma unroll
    for (int s=0;s<NS-1;s++) load(s);
    for (int c=0;c<NC;c++){
        if (c+1<NC && NS>2) asm volatile("cp.async.wait_group %0;"::"n"(NS-2):"memory");
        else if (NS>2)      asm volatile("cp.async.wait_group 0;":::"memory");
        else                asm volatile("cp.async.wait_group 0;":::"memory");
        __syncthreads();
        if (c+NS-1<NC) load(c+NS-1);
        uint32_t sA = sb + (uint32_t)(c%NS)*STG;
        uint32_t sB = sA + 16384u;
        #pragma unroll
        for (int s=0;s<4;s++){
            uint32_t af[2][4];
            #pragma unroll
            for (int i=0;i<2;i++){
                uint32_t a = sA + swz((uint32_t)((wy*32 + i*16 + lr)*128 + s*32 + lg*16));
                ldsm4(af[i][0],af[i][1],af[i][2],af[i][3], a);
            }
            #pragma unroll
            for (int j=0;j<WN/16;j++){
                uint32_t b0,b1,b2,b3;
                uint32_t a = sB + swz((uint32_t)((wx*WN + j*16 + lr)*128 + s*32 + lg*16));
                ldsm4(b0,b1,b2,b3, a);
                #pragma unroll
                for (int i=0;i<2;i++){
                    mma16816(acc[i][2*j  ], af[i][0],af[i][1],af[i][2],af[i][3], b0,b2);
                    mma16816(acc[i][2*j+1], af[i][0],af[i][1],af[i][2],af[i][3], b1,b3);
                }
            }
        }
    }

    #pragma unroll
    for (int i=0;i<2;i++){
        int row0 = bm + wy*32 + i*16 + (l>>2);
        #pragma unroll
        for (int j=0;j<WN/8;j++){
            int col = bn + wx*WN + j*8 + (l&3)*2;
            float bx=0.f, by=0.f;
            if (bias){ bx = bias[col]; by = bias[col+1]; }
            float2 v0 = make_float2(acc[i][j][0]+bx, acc[i][j][1]+by);
            float2 v1 = make_float2(acc[i][j][2]+bx, acc[i][j][3]+by);
            *reinterpret_cast<float2*>(C + (size_t)row0*N + col)     = v0;
            *reinterpret_cast<float2*>(C + (size_t)(row0+8)*N + col) = v1;
        }
    }
}

template<int BN, int NS>
__global__ void __launch_bounds__(256, 1)
mgemm(const bf16* __restrict__ A, const bf16* __restrict__ B,
      const float* __restrict__ bias, float* __restrict__ C, int N, int K)
{
    extern __shared__ char smem[];
    gemm_body<BN,NS>(A, B, bias, C, blockIdx.y<<7, blockIdx.x*BN, N, K, smem);
}

// decoder fused launch: 256 uniform CTAs (K'=3072 each):
//   id<192 : gh(t)   = act  @ whhd^T + bhh_d   (1024x3072)
//   id>=192: hw2(t-1)= actH @ w2t^T            (1024x1024)
__global__ void __launch_bounds__(256, 2)
mgemm_pair(const bf16* __restrict__ act, const bf16* __restrict__ whhd,
           const float* __restrict__ bhh, float* __restrict__ Cgh,
           const bf16* __restrict__ actH, const bf16* __restrict__ w2t,
           float* __restrict__ Chw2)
{
    extern __shared__ char smem[];
    int id = blockIdx.x;
    if (id < 192)
        gemm_body<128,3>(act, whhd, bhh, Cgh, (id/24)<<7, (id%24)<<7, H3, 3*Hh, smem);
    else {
        id -= 192;
        gemm_body<128,3>(actH, w2t, nullptr, Chw2, (id>>3)<<7, (id&7)<<7, Hh, 3*Hh, smem);
    }
}

// ---- split kernels (one-time operands) ----
__global__ void splitA(const float* __restrict__ s, bf16* __restrict__ d, int ksh){
    int i = blockIdx.x*256 + threadIdx.x;
    int K = 1<<ksh, r = i>>ksh, c = i&(K-1);
    split3(s[i], d, (size_t)r*3*K, K, c);
}
__global__ void splitB(const float* __restrict__ s, bf16* __restrict__ d, int ksh){
    int i = blockIdx.x*256 + threadIdx.x;
    int K = 1<<ksh, r = i>>ksh, c = i&(K-1);
    float x = s[i];
    bf16 h = __float2bfloat16(x);
    bf16 lo = __float2bfloat16(x - __bfloat162float(h));
    size_t base = (size_t)r*3*K + c;
    d[base] = h; d[base+K] = h; d[base+2*K] = lo;
}
__global__ void tsplitB(const float* __restrict__ W, bf16* __restrict__ d){
    __shared__ float t[32][33];
    int bx = blockIdx.x<<5, by = blockIdx.y<<5, x = threadIdx.x, y = threadIdx.y;
    #pragma unroll
    for (int j=0;j<32;j+=8) t[y+j][x] = W[(size_t)(by+y+j)*Hh + bx+x];
    __syncthreads();
    #pragma unroll
    for (int j=0;j<32;j+=8){
        float v = t[x][y+j];
        bf16 h = __float2bfloat16(v);
        bf16 lo = __float2bfloat16(v - __bfloat162float(h));
        size_t base = (size_t)(bx+y+j)*3*Hh + (by+x);
        d[base] = h; d[base+Hh] = h; d[base+2*Hh] = lo;
    }
}

// ---- fused small kernels ----
__global__ void setup_kernel(const float* __restrict__ phis){
    int id = blockIdx.x*256 + threadIdx.x; if (id >= Bb*Nn) return;
    int b = id>>4, n = id&15;
    const float* prow = phis + (size_t)(b*Nn+n)*Nn;
    float s=0.f;
    #pragma unroll
    for (int k=0;k<Nn;k++) s += prow[k];
    int ns = (int)(s+0.5f);
    g_tgate[n*Bb+b] = (n==0)?1.0f:prow[n-1];
    g_idx[n*Bb+b] = (ns+n-1)&(Nn-1);
}
__global__ void zero_init(){
    int i = blockIdx.x*256+threadIdx.x;
    g_act[i] = __float2bfloat16(0.f);
    if (i < Bb*Hh) g_h[i] = 0.f;
}
__global__ void enc_combine(int t){
    int id = blockIdx.x*256+threadIdx.x; int b=id>>10, h=id&1023;
    float tg = g_tgate[t*Bb+b];
    float hg = tg*g_h[id];
    const float* gi = g_gie + (size_t)(b*Nn+t)*H3;
    const float* gh = g_gh + (size_t)b*H3;
    float r = fsig(gi[h]+gh[h]);
    float z = fsig(gi[Hh+h]+gh[Hh+h]);
    float g = ftanh(gi[2*Hh+h]+r*gh[2*Hh+h]);
    float hn = (1.0f-z)*g + z*hg;
    g_h[id]=hn; g_henc[(size_t)(b*Nn+t)*Hh+h]=hn;
    if (t < Nn-1)
        split3(g_tgate[(t+1)*Bb+b]*hn, g_act, (size_t)b*3*Hh, Hh, h);
}
// decoder init: h(-1)=heff(0)=h0 (idx0 == hidden0 index; tg(0)=1), ip(0)=itok
__global__ void dec_init(const float* __restrict__ it){
    int id = blockIdx.x*256+threadIdx.x; int b=id>>10, h=id&1023;
    float h0 = g_henc[(size_t)(b*Nn+g_idx[b])*Hh+h];
    g_h[id] = h0; g_heff[id] = h0;
    split3(h0, g_act, (size_t)b*3*Hh, Hh, h);
    if (h<Ii) split3(it[h], g_ip, (size_t)b*3*Ii, Ii, h);
}
// GRU combine: h(t); split h(t) -> actH (hw2); heff(t+1) + split -> act
__global__ void dec_combine(int t){
    int id = blockIdx.x*256+threadIdx.x; int b=id>>10, h=id&1023;
    const float* gi = g_gid + (size_t)b*H3;
    const float* gh = g_gh + (size_t)b*H3;
    float r = fsig(gi[h]+gh[h]);
    float z = fsig(gi[Hh+h]+gh[Hh+h]);
    float g = ftanh(gi[2*Hh+h]+r*gh[2*Hh+h]);
    float hn = (1.0f-z)*g + z*g_heff[id];
    g_h[id] = hn;
    split3(hn, g_actH, (size_t)b*3*Hh, Hh, h);
    if (t < Nn-1){
        float tg = g_tgate[(t+1)*Bb+b];
        float ih = g_henc[(size_t)(b*Nn+g_idx[(t+1)*Bb+b])*Hh+h];
        float he = tg*hn + (1.0f-tg)*ih;
        g_heff[id] = he;
        split3(he, g_act, (size_t)b*3*Hh, Hh, h);
    }
}
// fused: u logits + masked softmax + context matvec + gated ip(t+1) split
__global__ void attn_fused(const float* __restrict__ v, const float* __restrict__ phis,
                           const float* __restrict__ input, const float* __restrict__ it,
                           float* __restrict__ out, int t, int write_ip){
    __shared__ float su[Nn];
    __shared__ float sat[Nn];
    int b = blockIdx.x, tid = threadIdx.x, w = tid>>5, l = tid&31;
    const float4* hrow = reinterpret_cast<const float4*>(g_hw2 + (size_t)b*Hh);
    const float4* vv4  = reinterpret_cast<const float4*>(v);
    #pragma unroll
    for (int nn=0; nn<2; nn++){
        int n = w + nn*8;
        const float4* wrow = reinterpret_cast<const float4*>(g_w1xe + (size_t)(b*Nn+n)*Hh);
        float s = 0.f;
        #pragma unroll
        for (int i=l; i<256; i+=32){
            float4 a = wrow[i], h4 = hrow[i], vv = vv4[i];
            s += ftanh(a.x+h4.x)*vv.x + ftanh(a.y+h4.y)*vv.y
               + ftanh(a.z+h4.z)*vv.z + ftanh(a.w+h4.w)*vv.w;
        }
        #pragma unroll
        for (int o=16;o;o>>=1) s += __shfl_xor_sync(0xffffffffu, s, o);
        if (l==0) su[n] = s;
    }
    __syncthreads();
    if (tid<Nn){
        float mask = phis[(size_t)(b*Nn+t)*Nn+tid];
        float um = su[tid]*mask;
        float m = um;
        #pragma unroll
        for (int o=8;o;o>>=1) m = fmaxf(m, __shfl_xor_sync(0xffffu, m, o));
        float e = __expf(um-m)*mask;
        float ss = e;
        #pragma unroll
        for (int o=8;o;o>>=1) ss += __shfl_xor_sync(0xffffu, ss, o);
        float a = e/ss;
        sat[tid]=a;
        out[(size_t)(b*Nn+t)*Nn+tid]=a;
    }
    __syncthreads();
    if (write_ip){
        float s = 0.f;
        const float* irow = input + (size_t)b*Nn*Ii + tid;
        #pragma unroll
        for (int n=0;n<Nn;n++) s += sat[n]*irow[n*Ii];
        float tg = g_tgate[(t+1)*Bb+b];
        float ni = tg*s + (1.0f-tg)*it[tid];
        split3(ni, g_ip, (size_t)b*3*Ii, Ii, tid);
    }
}

// ---- driver ----
#define SYM(p,s) cudaGetSymbolAddress((void**)&p, s)
extern "C" void kernel_launch(void* const* d_in, const int* in_sizes, int n_in,
                              void* d_out, int out_size){
    const float* input=(const float*)d_in[0];  const float* phis =(const float*)d_in[1];
    const float* itok =(const float*)d_in[2];  const float* W1   =(const float*)d_in[3];
    const float* W2   =(const float*)d_in[4];  const float* v    =(const float*)d_in[5];
    const float* Wih_e=(const float*)d_in[6];  const float* Whh_e=(const float*)d_in[7];
    const float* bih_e=(const float*)d_in[8];  const float* bhh_e=(const float*)d_in[9];
    const float* Wih_d=(const float*)d_in[10]; const float* Whh_d=(const float*)d_in[11];
    const float* bih_d=(const float*)d_in[12]; const float* bhh_d=(const float*)d_in[13];
    float* out=(float*)d_out;

    float *p_gie,*p_henc,*p_w1xe,*p_gh,*p_gid,*p_hw2;
    SYM(p_gie,g_gie); SYM(p_henc,g_henc); SYM(p_w1xe,g_w1xe);
    SYM(p_gh,g_gh); SYM(p_gid,g_gid); SYM(p_hw2,g_hw2);
    bf16 *inA,*hencA,*act,*actH,*ip,*wihe,*whhe,*wihd,*whhd,*w1t,*w2t;
    SYM(inA,g_inA); SYM(hencA,g_hencA); SYM(act,g_act); SYM(actH,g_actH); SYM(ip,g_ip);
    SYM(wihe,g_wihe); SYM(whhe,g_whhe); SYM(wihd,g_wihd); SYM(whhd,g_whhd);
    SYM(w1t,g_w1t); SYM(w2t,g_w2t);

    const int SM128 = 3*(16384 + 128*128);   // 98304 (3-stage)
    const int SM192 = 2*(16384 + 192*128);   // 81920 (2-stage)
    const int SM64  = 3*(16384 + 64*128);    // 73728
    cudaFuncSetAttribute((void*)mgemm<128,3>, cudaFuncAttributeMaxDynamicSharedMemorySize, SM128);
    cudaFuncSetAttribute((void*)mgemm<192,2>, cudaFuncAttributeMaxDynamicSharedMemorySize, SM192);
    cudaFuncSetAttribute((void*)mgemm<64,3>,  cudaFuncAttributeMaxDynamicSharedMemorySize, SM64);
    cudaFuncSetAttribute((void*)mgemm_pair,   cudaFuncAttributeMaxDynamicSharedMemorySize, SM128);
    const int EW = (Bb*Hh)/256;

    // prologue (4th launch = big mgemm, for ncu -s targeting)
    setup_kernel<<<(Bb*Nn+255)/256,256>>>(phis);                 // 1
    splitB<<<(H3*Ii)/256,256>>>(Wih_e, wihe, 8);                 // 2
    splitA<<<(Bb*Nn*Ii)/256,256>>>(input, inA, 8);               // 3
    mgemm<128,3><<<dim3(H3/128,(Bb*Nn)/128),256,SM128>>>(        // 4 <- profiled
        inA, wihe, bih_e, p_gie, H3, 3*Ii);
    zero_init<<<(Bb*3*Hh)/256,256>>>();
    splitB<<<(H3*Hh)/256,256>>>(Whh_e, whhe, 10);
    splitB<<<(H3*Ii)/256,256>>>(Wih_d, wihd, 8);
    splitB<<<(H3*Hh)/256,256>>>(Whh_d, whhd, 10);
    tsplitB<<<dim3(32,32),dim3(32,8)>>>(W1, w1t);
    tsplitB<<<dim3(32,32),dim3(32,8)>>>(W2, w2t);

    // encoder: balanced BN=192 tiles (128 CTAs, one wave)
    for (int t=0;t<Nn;t++){
        mgemm<192,2><<<dim3(H3/192,Bb/128),256,SM192>>>(act, whhe, bhh_e, p_gh, H3, 3*Hh);
        enc_combine<<<EW,256>>>(t);
    }

    // W1xe = henc @ W1
    splitA<<<(Bb*Nn*Hh)/256,256>>>(p_henc, hencA, 10);
    mgemm<128,3><<<dim3(Hh/128,(Bb*Nn)/128),256,SM128>>>(hencA, w1t, nullptr, p_w1xe, Hh, 3*Hh);

    dec_init<<<EW,256>>>(itok);
    // decoder
    for (int t=0;t<Nn;t++){
        if (t==0)
            mgemm<192,2><<<dim3(H3/192,Bb/128),256,SM192>>>(act, whhd, bhh_d, p_gh, H3, 3*Hh);
        else {
            mgemm_pair<<<256,256,SM128>>>(act, whhd, bhh_d, p_gh, actH, w2t, p_hw2);
            attn_fused<<<Bb,256>>>(v, phis, input, itok, out, t-1, 1);
        }
        mgemm<128,3><<<dim3(H3/128,Bb/128),256,SM128>>>(ip, wihd, bih_d, p_gid, H3, 3*Ii);
        dec_combine<<<EW,256>>>(t);
    }
    mgemm<64,3><<<dim3(Hh/64,Bb/128),256,SM64>>>(actH, w2t, nullptr, p_hw2, Hh, 3*Hh);
    attn_fused<<<Bb,256>>>(v, phis, input, itok, out, Nn-1, 0);
}